// round 12
// baseline (speedup 1.0000x reference)
#include <cuda_runtime.h>
#include <math.h>
#include <stdint.h>

#define NROW 9216   // L*B = 576*16
#define NBLK 100    // persistent grid size (<=148 SMs -> co-resident, barrier safe)

// ---------------- static device scratch (no allocations) ----------------
__device__ __align__(16) float g_x[NROW * 41];
__device__ __align__(16) float g_projF[576 * 3200 * 16];   // [t][gate][b]
__device__ __align__(16) float g_projB[576 * 3200 * 16];
__device__ __align__(16) float g_h0[NROW * 1600];          // [t*16+b][1600]
__device__ __align__(16) float g_h1[NROW * 1600];
__device__ __align__(16) float g_hbuf[2][2][12800];        // [parity][dir][u*16+b]
__device__ __align__(16) float g_logits[NROW * 60];
__device__ __align__(16) float g_srf[1728 * 16 * 3];
__device__ __align__(16) float g_frag[72 * 24 * 16 * 3];   // [f][kfrag][b][3]

__device__ unsigned g_bar_count;   // zero-init; returns to 0 after every barrier
__device__ unsigned g_bar_phase;   // monotone across replays (equality-tested)

// ---------------- packed f32x2 helpers (2x FFMA throughput on sm_103a) ----------------
__device__ __forceinline__ void fma2(unsigned long long& acc, unsigned long long a,
                                     unsigned long long b) {
    asm("fma.rn.f32x2 %0, %1, %2, %0;" : "+l"(acc) : "l"(a), "l"(b));
}
__device__ __forceinline__ unsigned long long bcast2(float x) {
    unsigned long long r;
    asm("mov.b64 %0, {%1, %1};" : "=l"(r) : "f"(x));
    return r;
}
__device__ __forceinline__ unsigned long long pack2(float x, float y) {
    unsigned long long r;
    asm("mov.b64 %0, {%1, %2};" : "=l"(r) : "f"(x), "f"(y));
    return r;
}
__device__ __forceinline__ float2 unpack2(unsigned long long v) {
    float2 r;
    asm("mov.b64 {%0, %1}, %2;" : "=f"(r.x), "=f"(r.y) : "l"(v));
    return r;
}

// ---------------- fast activations (HW tanh) ----------------
__device__ __forceinline__ float fast_tanh(float x) {
    float y;
    asm("tanh.approx.f32 %0, %1;" : "=f"(y) : "f"(x));
    return y;
}
__device__ __forceinline__ float fast_sig(float x) {
    return 0.5f * fast_tanh(0.5f * x) + 0.5f;
}

// ---------------- software grid barrier (all NBLK CTAs co-resident) ----------------
__device__ __forceinline__ void grid_bar() {
    __threadfence();
    __syncthreads();
    if (threadIdx.x == 0) {
        volatile unsigned* ph = &g_bar_phase;
        unsigned p = *ph;                       // read BEFORE arriving (monotone-safe)
        unsigned a = atomicAdd(&g_bar_count, 1u);
        if (a == NBLK - 1u) {
            g_bar_count = 0u;
            __threadfence();                    // reset visible before release
            *ph = p + 1u;
        } else {
            while (*ph == p) { }
        }
        __threadfence();
    }
    __syncthreads();
}

// ---------------- input assembly: one_hot(seq,20) ++ pssm ----------------
__global__ void build_x(const int* __restrict__ seq, const float* __restrict__ pssm) {
    int i = blockIdx.x * blockDim.x + threadIdx.x;
    if (i >= NROW * 41) return;
    int row = i / 41, k = i - row * 41;
    float v;
    if (k < 20) v = (seq[row] == k) ? 1.0f : 0.0f;
    else        v = pssm[(size_t)row * 21 + (k - 20)];
    g_x[i] = v;
}

// ---------------- fp32x2 SGEMM (NT): C[m][n] = sum_k A[m][k]*B[n][k] + biases ----------------
// BM=BN=128, BK=16, 256 threads, 8x8 per-thread tile via packed f32x2.
// Asel: 0=g_x, 1=g_h0, 2=g_h1.  Csel: 0=g_projF, 1=g_projB, 2=g_logits.
// mode 0: C[m*N+n];  mode 1 (proj layout): C[((m>>4)*N + n)*16 + (m&15)]
__global__ void __launch_bounds__(256) sgemm_nt(
    int Asel, const float* __restrict__ B,
    const float* __restrict__ bias1, const float* __restrict__ bias2,
    int Csel, int M, int N, int K, int mode)
{
    __shared__ __align__(16) float As[16][128];
    __shared__ __align__(16) float Bs[16][128];
    const float* A = (Asel == 0) ? g_x : ((Asel == 1) ? g_h0 : g_h1);
    float* C = (Csel == 0) ? g_projF : ((Csel == 1) ? g_projB : g_logits);

    int tid = threadIdx.x;
    int tx = tid & 15, ty = tid >> 4;
    int mB = blockIdx.y * 128, nB = blockIdx.x * 128;
    unsigned long long acc[8][4];
#pragma unroll
    for (int i = 0; i < 8; i++)
#pragma unroll
        for (int j = 0; j < 4; j++) acc[i][j] = 0ull;

    bool k16 = ((K & 15) == 0);

    for (int k0 = 0; k0 < K; k0 += 16) {
        if (k16) {
#pragma unroll
            for (int e = 0; e < 2; e++) {
                int fid = tid + e * 256;         // 0..511
                int row = fid >> 2;              // 0..127
                int kc  = (fid & 3) << 2;        // 0,4,8,12
                float4 va = *reinterpret_cast<const float4*>(A + (size_t)(mB + row) * K + k0 + kc);
                As[kc + 0][row] = va.x; As[kc + 1][row] = va.y;
                As[kc + 2][row] = va.z; As[kc + 3][row] = va.w;
                float4 vb = make_float4(0.f, 0.f, 0.f, 0.f);
                if (nB + row < N)
                    vb = *reinterpret_cast<const float4*>(B + (size_t)(nB + row) * K + k0 + kc);
                Bs[kc + 0][row] = vb.x; Bs[kc + 1][row] = vb.y;
                Bs[kc + 2][row] = vb.z; Bs[kc + 3][row] = vb.w;
            }
        } else {
            int row = tid >> 1;
            int c0  = (tid & 1) * 8;
#pragma unroll
            for (int u = 0; u < 8; u++) {
                int k = k0 + c0 + u;
                As[c0 + u][row] = (k < K) ? A[(size_t)(mB + row) * K + k] : 0.0f;
                Bs[c0 + u][row] = (k < K && (nB + row) < N) ? B[(size_t)(nB + row) * K + k] : 0.0f;
            }
        }
        __syncthreads();
#pragma unroll
        for (int kk = 0; kk < 16; kk++) {
            float4 a0 = *reinterpret_cast<const float4*>(&As[kk][ty * 8]);
            float4 a1 = *reinterpret_cast<const float4*>(&As[kk][ty * 8 + 4]);
            ulonglong2 bL = *reinterpret_cast<const ulonglong2*>(&Bs[kk][tx * 8]);
            ulonglong2 bH = *reinterpret_cast<const ulonglong2*>(&Bs[kk][tx * 8 + 4]);
            float av[8] = {a0.x, a0.y, a0.z, a0.w, a1.x, a1.y, a1.z, a1.w};
#pragma unroll
            for (int i = 0; i < 8; i++) {
                unsigned long long ai = bcast2(av[i]);
                fma2(acc[i][0], ai, bL.x);
                fma2(acc[i][1], ai, bL.y);
                fma2(acc[i][2], ai, bH.x);
                fma2(acc[i][3], ai, bH.y);
            }
        }
        __syncthreads();
    }

#pragma unroll
    for (int i = 0; i < 8; i++) {
        int m = mB + ty * 8 + i;
#pragma unroll
        for (int j = 0; j < 4; j++) {
            float2 v2 = unpack2(acc[i][j]);
            float vv[2] = {v2.x, v2.y};
#pragma unroll
            for (int e = 0; e < 2; e++) {
                int n = nB + tx * 8 + 2 * j + e;
                if (n < N) {
                    float v = vv[e];
                    if (bias1) v += bias1[n];
                    if (bias2) v += bias2[n];
                    if (mode == 0) C[(size_t)m * N + n] = v;
                    else           C[(((size_t)(m >> 4)) * N + n) * 16 + (m & 15)] = v;
                }
            }
        }
    }
}

// ---------------- persistent bi-LSTM layer ----------------
// 100 CTAs: dir = bx&1, gblk = bx>>1 (0..49). Each CTA owns units
// u in [gblk*16, gblk*16+16): its 64 gate rows {u, u+800, u+1600, u+2400}
// stay in CTA-local smem; cell state c is a per-thread register.
// Only h crosses CTAs: double-buffered global + one grid barrier per step.
__global__ void __launch_bounds__(256, 1) lstm_layer(
    int layer, const float* __restrict__ WhhF, const float* __restrict__ WhhB)
{
    extern __shared__ float smem[];
    float* hs  = smem;            // 12800 floats: full h_{s-1}, [u*16+b]
    float* gsm = smem + 12800;    // 1024 floats: own gates [gate][ul][b]

    int bx = blockIdx.x;
    int dir = bx & 1, gblk = bx >> 1;
    int tid = threadIdx.x;
    const float* Whh  = dir ? WhhB : WhhF;
    const float* proj = dir ? g_projB : g_projF;
    float* hseq = layer ? g_h1 : g_h0;

    // phase-A mapping (one h element per thread)
    int ua = tid >> 4, b = tid & 15;           // ua 0..15
    int u  = gblk * 16 + ua;                   // global unit
    // matmul mapping (one gate row x 4 batches per thread)
    int gi2 = tid >> 6;                        // gate 0..3
    int ul  = (tid >> 2) & 15;
    int q   = tid & 3;
    int r   = gi2 * 800 + gblk * 16 + ul;      // global gate row
    const float4* W4 = reinterpret_cast<const float4*>(Whh + (size_t)r * 800);
    const ulonglong2* hs2 = reinterpret_cast<const ulonglong2*>(hs);

    float c_reg = 0.0f;

    for (int s = 0; s <= 576; s++) {
        // ---- phase A: finalize h_{s-1}, c_{s-1} from own gates ----
        if (s > 0) {
            float gi = gsm[0 * 256 + ua * 16 + b];
            float gf = gsm[1 * 256 + ua * 16 + b];
            float gg = gsm[2 * 256 + ua * 16 + b];
            float go = gsm[3 * 256 + ua * 16 + b];
            float cn = fast_sig(gf) * c_reg + fast_sig(gi) * fast_tanh(gg);
            c_reg = cn;
            float h = fast_sig(go) * fast_tanh(cn);
            g_hbuf[(s - 1) & 1][dir][u * 16 + b] = h;
            int tprev = dir ? (576 - s) : (s - 1);
            hseq[(size_t)(tprev * 16 + b) * 1600 + dir * 800 + u] = h;
        }
        if (s == 576) break;
        grid_bar();                           // h_{s-1} visible to all CTAs

        // ---- broadcast h into smem (L2 path: L1 is stale across iterations) ----
        if (s == 0) {
            for (int e4 = tid; e4 < 3200; e4 += 256)
                reinterpret_cast<float4*>(hs)[e4] = make_float4(0.f, 0.f, 0.f, 0.f);
        } else {
            const float4* hb = reinterpret_cast<const float4*>(g_hbuf[(s - 1) & 1][dir]);
            for (int e4 = tid; e4 < 3200; e4 += 256)
                reinterpret_cast<float4*>(hs)[e4] = __ldcg(hb + e4);
        }
        __syncthreads();

        // ---- gates_s[r][q] = proj_s[r][q] + Whh[r,:] @ h ----
        int t = dir ? (575 - s) : s;
        float4 pv = *reinterpret_cast<const float4*>(proj + ((size_t)t * 3200 + r) * 16 + q * 4);
        unsigned long long a0 = pack2(pv.x, pv.y);
        unsigned long long a1 = pack2(pv.z, pv.w);
#pragma unroll 4
        for (int kb = 0; kb < 200; kb++) {
            float4 w = W4[kb];
            unsigned long long w0 = bcast2(w.x), w1 = bcast2(w.y);
            unsigned long long w2 = bcast2(w.z), w3 = bcast2(w.w);
            ulonglong2 hA = hs2[(4 * kb + 0) * 4 + q];
            ulonglong2 hB = hs2[(4 * kb + 1) * 4 + q];
            ulonglong2 hC = hs2[(4 * kb + 2) * 4 + q];
            ulonglong2 hD = hs2[(4 * kb + 3) * 4 + q];
            fma2(a0, w0, hA.x); fma2(a1, w0, hA.y);
            fma2(a0, w1, hB.x); fma2(a1, w1, hB.y);
            fma2(a0, w2, hC.x); fma2(a1, w2, hC.y);
            fma2(a0, w3, hD.x); fma2(a1, w3, hD.y);
        }
        float2 r0 = unpack2(a0), r1 = unpack2(a1);
        *reinterpret_cast<float4*>(gsm + gi2 * 256 + ul * 16 + q * 4) =
            make_float4(r0.x, r0.y, r1.x, r1.y);
        __syncthreads();                      // gsm ready for next phase A
    }
}

// ---------------- softmax + angle mixing + SRF (softmax denom cancels in atan2) ----------------
__global__ void phisrf(const float* __restrict__ alphabet,
                       const float* __restrict__ blen, const float* __restrict__ bang) {
    __shared__ float sA[180], cA[180];
    int tid = threadIdx.x;
    if (tid < 180) { float a = alphabet[tid]; sA[tid] = sinf(a); cA[tid] = cosf(a); }
    __syncthreads();
    int row = blockIdx.x * 256 + tid;
    if (row >= NROW) return;
    const float* z = g_logits + (size_t)row * 60;
    float mx = -1e30f;
    for (int j = 0; j < 60; j++) mx = fmaxf(mx, z[j]);
    float ss0 = 0, ss1 = 0, ss2 = 0, sc0 = 0, sc1 = 0, sc2 = 0;
    for (int j = 0; j < 60; j++) {
        float e = __expf(z[j] - mx);
        ss0 += e * sA[j * 3 + 0]; sc0 += e * cA[j * 3 + 0];
        ss1 += e * sA[j * 3 + 1]; sc1 += e * cA[j * 3 + 1];
        ss2 += e * sA[j * 3 + 2]; sc2 += e * cA[j * 3 + 2];
    }
    float ss[3] = {ss0, ss1, ss2}, sc[3] = {sc0, sc1, sc2};
    int l = row >> 4, b = row & 15;
#pragma unroll
    for (int d = 0; d < 3; d++) {
        float rh = rsqrtf(ss[d] * ss[d] + sc[d] * sc[d]);
        float cp = sc[d] * rh, sp = ss[d] * rh;       // cos/sin of atan2(ss, sc)
        float rr = blen[d], th = bang[d];
        float sth = sinf(th), cth = cosf(th);
        float* o = &g_srf[(((size_t)(3 * l + d)) * 16 + b) * 3];
        o[0] = rr * cth;
        o[1] = rr * cp * sth;
        o[2] = rr * sp * sth;
    }
}

// ---------------- pNeRF: 384 parallel scan chains + sequential fragment assembly ----------------
struct F3 { float x, y, z; };
__device__ __forceinline__ F3 mk3(float x, float y, float z) { F3 r; r.x = x; r.y = y; r.z = z; return r; }
__device__ __forceinline__ F3 sub3(F3 a, F3 b) { return mk3(a.x - b.x, a.y - b.y, a.z - b.z); }
__device__ __forceinline__ F3 crs3(F3 a, F3 b) {
    return mk3(a.y * b.z - a.z * b.y, a.z * b.x - a.x * b.z, a.x * b.y - a.y * b.x);
}
__device__ __forceinline__ F3 unit3(F3 v) {
    float r = rsqrtf(v.x * v.x + v.y * v.y + v.z * v.z);
    return mk3(v.x * r, v.y * r, v.z * r);
}

__global__ void pnerf_kernel(float* __restrict__ out) {
    __shared__ float Rm[16][9];
    __shared__ float Og[16][3];
    int tid = threadIdx.x;                     // 384 threads
    {
        int kf = tid >> 4, b = tid & 15;       // chain (fragment, batch)
        F3 A  = mk3(-0.70710678118654752f, 1.22474487139158905f, 0.f);
        F3 Bp = mk3(-1.41421356237309505f, 0.f, 0.f);
        F3 C  = mk3(0.f, 0.f, 0.f);
        for (int f = 0; f < 72; f++) {
            const float* ct = &g_srf[(((size_t)(kf * 72 + f)) * 16 + b) * 3];
            F3 bc = unit3(sub3(C, Bp));
            F3 n  = unit3(crs3(sub3(Bp, A), bc));
            F3 m  = crs3(n, bc);
            F3 D  = mk3(C.x + bc.x * ct[0] + m.x * ct[1] + n.x * ct[2],
                        C.y + bc.y * ct[0] + m.y * ct[1] + n.y * ct[2],
                        C.z + bc.z * ct[0] + m.z * ct[1] + n.z * ct[2]);
            float* fp = &g_frag[((((size_t)f) * 24 + kf) * 16 + b) * 3];
            fp[0] = D.x; fp[1] = D.y; fp[2] = D.z;
            A = Bp; Bp = C; C = D;
        }
    }
    __syncthreads();
    for (int e = tid; e < 72 * 16; e += 384) {
        int f = e >> 4, b = e & 15;
        const float* fp = &g_frag[((((size_t)f) * 24 + 0) * 16 + b) * 3];
        float* o = &out[((size_t)f * 16 + b) * 3];
        o[0] = fp[0]; o[1] = fp[1]; o[2] = fp[2];
    }
    __syncthreads();
    for (int k = 1; k < 24; k++) {
        if (tid < 16) {
            int base = 72 * k;
            const float* pa = &out[((size_t)(base - 3) * 16 + tid) * 3];
            const float* pb = &out[((size_t)(base - 2) * 16 + tid) * 3];
            const float* pc = &out[((size_t)(base - 1) * 16 + tid) * 3];
            F3 A  = mk3(pa[0], pa[1], pa[2]);
            F3 B2 = mk3(pb[0], pb[1], pb[2]);
            F3 C  = mk3(pc[0], pc[1], pc[2]);
            F3 bc = unit3(sub3(C, B2));
            F3 n  = unit3(crs3(sub3(B2, A), bc));
            F3 m  = crs3(n, bc);
            Rm[tid][0] = bc.x; Rm[tid][1] = bc.y; Rm[tid][2] = bc.z;
            Rm[tid][3] = m.x;  Rm[tid][4] = m.y;  Rm[tid][5] = m.z;
            Rm[tid][6] = n.x;  Rm[tid][7] = n.y;  Rm[tid][8] = n.z;
            Og[tid][0] = C.x;  Og[tid][1] = C.y;  Og[tid][2] = C.z;
        }
        __syncthreads();
        for (int e = tid; e < 72 * 16; e += 384) {
            int f = e >> 4, b = e & 15;
            const float* fp = &g_frag[((((size_t)f) * 24 + k) * 16 + b) * 3];
            float vx = fp[0], vy = fp[1], vz = fp[2];
            float* o = &out[((size_t)(72 * k + f) * 16 + b) * 3];
            o[0] = Og[b][0] + Rm[b][0] * vx + Rm[b][3] * vy + Rm[b][6] * vz;
            o[1] = Og[b][1] + Rm[b][1] * vx + Rm[b][4] * vy + Rm[b][7] * vz;
            o[2] = Og[b][2] + Rm[b][2] * vx + Rm[b][5] * vy + Rm[b][8] * vz;
        }
        __syncthreads();
    }
}

// ---------------- launch ----------------
extern "C" void kernel_launch(void* const* d_in, const int* in_sizes, int n_in,
                              void* d_out, int out_size) {
    const int*   seq      = (const int*)  d_in[0];
    const float* pssm     = (const float*)d_in[1];
    const float* w_ih_l0f = (const float*)d_in[3];
    const float* w_hh_l0f = (const float*)d_in[4];
    const float* b_ih_l0f = (const float*)d_in[5];
    const float* b_hh_l0f = (const float*)d_in[6];
    const float* w_ih_l0b = (const float*)d_in[7];
    const float* w_hh_l0b = (const float*)d_in[8];
    const float* b_ih_l0b = (const float*)d_in[9];
    const float* b_hh_l0b = (const float*)d_in[10];
    const float* w_ih_l1f = (const float*)d_in[11];
    const float* w_hh_l1f = (const float*)d_in[12];
    const float* b_ih_l1f = (const float*)d_in[13];
    const float* b_hh_l1f = (const float*)d_in[14];
    const float* w_ih_l1b = (const float*)d_in[15];
    const float* w_hh_l1b = (const float*)d_in[16];
    const float* b_ih_l1b = (const float*)d_in[17];
    const float* b_hh_l1b = (const float*)d_in[18];
    const float* fc_w     = (const float*)d_in[19];
    const float* fc_b     = (const float*)d_in[20];
    const float* alphabet = (const float*)d_in[21];
    const float* blen     = (const float*)d_in[22];
    const float* bang     = (const float*)d_in[23];
    float* out = (float*)d_out;

    cudaFuncSetAttribute((const void*)lstm_layer,
                         cudaFuncAttributeMaxDynamicSharedMemorySize, 55296);

    build_x<<<(NROW * 41 + 255) / 256, 256>>>(seq, pssm);

    dim3 gProj(25, 72);
    // layer 0 input projections (K=41), biases folded in, [t][gate][b] layout
    sgemm_nt<<<gProj, 256>>>(0, w_ih_l0f, b_ih_l0f, b_hh_l0f, 0, NROW, 3200, 41, 1);
    sgemm_nt<<<gProj, 256>>>(0, w_ih_l0b, b_ih_l0b, b_hh_l0b, 1, NROW, 3200, 41, 1);
    lstm_layer<<<NBLK, 256, 55296>>>(0, w_hh_l0f, w_hh_l0b);

    // layer 1 input projections (K=1600)
    sgemm_nt<<<gProj, 256>>>(1, w_ih_l1f, b_ih_l1f, b_hh_l1f, 0, NROW, 3200, 1600, 1);
    sgemm_nt<<<gProj, 256>>>(1, w_ih_l1b, b_ih_l1b, b_hh_l1b, 1, NROW, 3200, 1600, 1);
    lstm_layer<<<NBLK, 256, 55296>>>(1, w_hh_l1f, w_hh_l1b);

    // FC -> logits (standard layout)
    sgemm_nt<<<dim3(1, 72), 256>>>(2, fc_w, fc_b, nullptr, 2, NROW, 60, 1600, 0);

    phisrf<<<36, 256>>>(alphabet, blen, bang);
    pnerf_kernel<<<1, 384>>>(out);
}

// round 13
// speedup vs baseline: 1.0516x; 1.0516x over previous
#include <cuda_runtime.h>
#include <math.h>
#include <stdint.h>

#define NROW 9216   // L*B = 576*16
#define NBLK 100    // persistent grid size (<=148 SMs -> co-resident, barrier safe)

// ---------------- static device scratch (no allocations) ----------------
__device__ __align__(16) float g_x[NROW * 41];
__device__ __align__(16) float g_projF[576 * 3200 * 16];   // [t][gate][b]
__device__ __align__(16) float g_projB[576 * 3200 * 16];
__device__ __align__(16) float g_h0[NROW * 1600];          // [t*16+b][1600]
__device__ __align__(16) float g_h1[NROW * 1600];
__device__ __align__(16) float g_hbuf[2][2][12800];        // [parity][dir][u*16+b]
__device__ __align__(16) float g_logits[NROW * 60];
__device__ __align__(16) float g_srf[1728 * 16 * 3];
__device__ __align__(16) float g_frag[72 * 24 * 16 * 3];   // [f][kfrag][b][3]

__device__ unsigned g_bar_count;   // zero-init; returns to 0 after every barrier
__device__ unsigned g_bar_phase;   // monotone across replays (equality-tested)

// ---------------- packed f32x2 helpers (2x FFMA throughput on sm_103a) ----------------
__device__ __forceinline__ void fma2(unsigned long long& acc, unsigned long long a,
                                     unsigned long long b) {
    asm("fma.rn.f32x2 %0, %1, %2, %0;" : "+l"(acc) : "l"(a), "l"(b));
}
__device__ __forceinline__ void add2(unsigned long long& acc, unsigned long long b) {
    asm("add.rn.f32x2 %0, %0, %1;" : "+l"(acc) : "l"(b));
}
__device__ __forceinline__ unsigned long long bcast2(float x) {
    unsigned long long r;
    asm("mov.b64 %0, {%1, %1};" : "=l"(r) : "f"(x));
    return r;
}
__device__ __forceinline__ unsigned long long pack2(float x, float y) {
    unsigned long long r;
    asm("mov.b64 %0, {%1, %2};" : "=l"(r) : "f"(x), "f"(y));
    return r;
}
__device__ __forceinline__ float2 unpack2(unsigned long long v) {
    float2 r;
    asm("mov.b64 {%0, %1}, %2;" : "=f"(r.x), "=f"(r.y) : "l"(v));
    return r;
}

// ---------------- acquire/release primitives (NO L1-flushing fences) ----------------
__device__ __forceinline__ unsigned atom_arrive_acqrel(unsigned* p) {
    unsigned old;
    asm volatile("atom.acq_rel.gpu.global.add.u32 %0, [%1], 1;"
                 : "=r"(old) : "l"(p) : "memory");
    return old;
}
__device__ __forceinline__ unsigned ld_acquire(const unsigned* p) {
    unsigned v;
    asm volatile("ld.acquire.gpu.global.u32 %0, [%1];" : "=r"(v) : "l"(p) : "memory");
    return v;
}
__device__ __forceinline__ unsigned ld_relaxed(const unsigned* p) {
    unsigned v;
    asm volatile("ld.relaxed.gpu.global.u32 %0, [%1];" : "=r"(v) : "l"(p) : "memory");
    return v;
}
__device__ __forceinline__ void st_release(unsigned* p, unsigned v) {
    asm volatile("st.release.gpu.global.u32 [%0], %1;" :: "l"(p), "r"(v) : "memory");
}
__device__ __forceinline__ void st_relaxed(unsigned* p, unsigned v) {
    asm volatile("st.relaxed.gpu.global.u32 [%0], %1;" :: "l"(p), "r"(v) : "memory");
}

// ---------------- fast activations (HW tanh) ----------------
__device__ __forceinline__ float fast_tanh(float x) {
    float y;
    asm("tanh.approx.f32 %0, %1;" : "=f"(y) : "f"(x));
    return y;
}
__device__ __forceinline__ float fast_sig(float x) {
    return 0.5f * fast_tanh(0.5f * x) + 0.5f;
}

// ---------------- input assembly: one_hot(seq,20) ++ pssm ----------------
__global__ void build_x(const int* __restrict__ seq, const float* __restrict__ pssm) {
    int i = blockIdx.x * blockDim.x + threadIdx.x;
    if (i >= NROW * 41) return;
    int row = i / 41, k = i - row * 41;
    float v;
    if (k < 20) v = (seq[row] == k) ? 1.0f : 0.0f;
    else        v = pssm[(size_t)row * 21 + (k - 20)];
    g_x[i] = v;
}

// ---------------- fp32x2 SGEMM (NT): C[m][n] = sum_k A[m][k]*B[n][k] + biases ----------------
__global__ void __launch_bounds__(256) sgemm_nt(
    int Asel, const float* __restrict__ B,
    const float* __restrict__ bias1, const float* __restrict__ bias2,
    int Csel, int M, int N, int K, int mode)
{
    __shared__ __align__(16) float As[16][128];
    __shared__ __align__(16) float Bs[16][128];
    const float* A = (Asel == 0) ? g_x : ((Asel == 1) ? g_h0 : g_h1);
    float* C = (Csel == 0) ? g_projF : ((Csel == 1) ? g_projB : g_logits);

    int tid = threadIdx.x;
    int tx = tid & 15, ty = tid >> 4;
    int mB = blockIdx.y * 128, nB = blockIdx.x * 128;
    unsigned long long acc[8][4];
#pragma unroll
    for (int i = 0; i < 8; i++)
#pragma unroll
        for (int j = 0; j < 4; j++) acc[i][j] = 0ull;

    bool k16 = ((K & 15) == 0);

    for (int k0 = 0; k0 < K; k0 += 16) {
        if (k16) {
#pragma unroll
            for (int e = 0; e < 2; e++) {
                int fid = tid + e * 256;         // 0..511
                int row = fid >> 2;              // 0..127
                int kc  = (fid & 3) << 2;        // 0,4,8,12
                float4 va = *reinterpret_cast<const float4*>(A + (size_t)(mB + row) * K + k0 + kc);
                As[kc + 0][row] = va.x; As[kc + 1][row] = va.y;
                As[kc + 2][row] = va.z; As[kc + 3][row] = va.w;
                float4 vb = make_float4(0.f, 0.f, 0.f, 0.f);
                if (nB + row < N)
                    vb = *reinterpret_cast<const float4*>(B + (size_t)(nB + row) * K + k0 + kc);
                Bs[kc + 0][row] = vb.x; Bs[kc + 1][row] = vb.y;
                Bs[kc + 2][row] = vb.z; Bs[kc + 3][row] = vb.w;
            }
        } else {
            int row = tid >> 1;
            int c0  = (tid & 1) * 8;
#pragma unroll
            for (int u = 0; u < 8; u++) {
                int k = k0 + c0 + u;
                As[c0 + u][row] = (k < K) ? A[(size_t)(mB + row) * K + k] : 0.0f;
                Bs[c0 + u][row] = (k < K && (nB + row) < N) ? B[(size_t)(nB + row) * K + k] : 0.0f;
            }
        }
        __syncthreads();
#pragma unroll
        for (int kk = 0; kk < 16; kk++) {
            float4 a0 = *reinterpret_cast<const float4*>(&As[kk][ty * 8]);
            float4 a1 = *reinterpret_cast<const float4*>(&As[kk][ty * 8 + 4]);
            ulonglong2 bL = *reinterpret_cast<const ulonglong2*>(&Bs[kk][tx * 8]);
            ulonglong2 bH = *reinterpret_cast<const ulonglong2*>(&Bs[kk][tx * 8 + 4]);
            float av[8] = {a0.x, a0.y, a0.z, a0.w, a1.x, a1.y, a1.z, a1.w};
#pragma unroll
            for (int i = 0; i < 8; i++) {
                unsigned long long ai = bcast2(av[i]);
                fma2(acc[i][0], ai, bL.x);
                fma2(acc[i][1], ai, bL.y);
                fma2(acc[i][2], ai, bH.x);
                fma2(acc[i][3], ai, bH.y);
            }
        }
        __syncthreads();
    }

#pragma unroll
    for (int i = 0; i < 8; i++) {
        int m = mB + ty * 8 + i;
#pragma unroll
        for (int j = 0; j < 4; j++) {
            float2 v2 = unpack2(acc[i][j]);
            float vv[2] = {v2.x, v2.y};
#pragma unroll
            for (int e = 0; e < 2; e++) {
                int n = nB + tx * 8 + 2 * j + e;
                if (n < N) {
                    float v = vv[e];
                    if (bias1) v += bias1[n];
                    if (bias2) v += bias2[n];
                    if (mode == 0) C[(size_t)m * N + n] = v;
                    else           C[(((size_t)(m >> 4)) * N + n) * 16 + (m & 15)] = v;
                }
            }
        }
    }
}

// ---------------- persistent bi-LSTM layer ----------------
// 100 CTAs: dir = bx&1, gblk = bx>>1 (0..49). Each CTA owns 16 units -> its 64
// gate rows stay in CTA-local smem; cell state in a register. Only h crosses
// CTAs (double-buffered global + one flush-free grid barrier per step).
// W stays L1-resident: no CCTL.IVALL anywhere in the loop; proj/h use .cg.
__global__ void __launch_bounds__(256, 1) lstm_layer(
    int layer, const float* __restrict__ WhhF, const float* __restrict__ WhhB)
{
    extern __shared__ float smem[];
    float* hs  = smem;            // 12800 floats: full h_{s-1}, [u*16+b]
    float* gsm = smem + 12800;    // 1024 floats: own gates [gate][ul][b]

    int bx = blockIdx.x;
    int dir = bx & 1, gblk = bx >> 1;
    int tid = threadIdx.x;
    const float* Whh  = dir ? WhhB : WhhF;
    const float* proj = dir ? g_projB : g_projF;
    float* hseq = layer ? g_h1 : g_h0;

    // local barrier phase (g_bar_phase is stable until the 100th arrival)
    unsigned my_phase = 0;
    if (tid == 0) my_phase = ld_relaxed(&g_bar_phase);

    // phase-A mapping (one h element per thread)
    int ua = tid >> 4, b = tid & 15;           // ua 0..15
    int u  = gblk * 16 + ua;                   // global unit
    // matmul mapping (one gate row x 4 batches per thread)
    int gi2 = tid >> 6;                        // gate 0..3
    int ul  = (tid >> 2) & 15;
    int q   = tid & 3;
    int r   = gi2 * 800 + gblk * 16 + ul;      // global gate row
    const float4* W4 = reinterpret_cast<const float4*>(Whh + (size_t)r * 800);
    const ulonglong2* hs2 = reinterpret_cast<const ulonglong2*>(hs);

    float c_reg = 0.0f;

    for (int s = 0; s <= 576; s++) {
        // ---- phase A: finalize h_{s-1}, c_{s-1} from own gates ----
        if (s > 0) {
            float gi = gsm[0 * 256 + ua * 16 + b];
            float gf = gsm[1 * 256 + ua * 16 + b];
            float gg = gsm[2 * 256 + ua * 16 + b];
            float go = gsm[3 * 256 + ua * 16 + b];
            float cn = fast_sig(gf) * c_reg + fast_sig(gi) * fast_tanh(gg);
            c_reg = cn;
            float h = fast_sig(go) * fast_tanh(cn);
            __stcg(&g_hbuf[(s - 1) & 1][dir][u * 16 + b], h);
            int tprev = dir ? (576 - s) : (s - 1);
            __stcg(&hseq[(size_t)(tprev * 16 + b) * 1600 + dir * 800 + u], h);
        }
        if (s == 576) break;

        // ---- flush-free grid barrier: h_{s-1} visible to all CTAs ----
        __syncthreads();
        if (tid == 0) {
            my_phase++;
            unsigned a = atom_arrive_acqrel(&g_bar_count);
            if (a == NBLK - 1u) {
                st_relaxed(&g_bar_count, 0u);        // ordered by release below
                st_release(&g_bar_phase, my_phase);
            } else {
                while (ld_acquire(&g_bar_phase) != my_phase) { }
            }
        }
        __syncthreads();

        // ---- broadcast h into smem (L2 path; W stays in L1) ----
        if (s == 0) {
            for (int e4 = tid; e4 < 3200; e4 += 256)
                reinterpret_cast<float4*>(hs)[e4] = make_float4(0.f, 0.f, 0.f, 0.f);
        } else {
            const float4* hb = reinterpret_cast<const float4*>(g_hbuf[(s - 1) & 1][dir]);
            for (int e4 = tid; e4 < 3200; e4 += 256)
                reinterpret_cast<float4*>(hs)[e4] = __ldcg(hb + e4);
        }
        __syncthreads();

        // ---- gates_s[r][q] = proj_s[r][q] + Whh[r,:] @ h (4 acc chains) ----
        int t = dir ? (575 - s) : s;
        float4 pv = __ldcg(reinterpret_cast<const float4*>(
                        proj + ((size_t)t * 3200 + r) * 16 + q * 4));
        unsigned long long a0 = pack2(pv.x, pv.y);
        unsigned long long a1 = pack2(pv.z, pv.w);
        unsigned long long b0 = 0ull, b1 = 0ull;
#pragma unroll 4
        for (int kb = 0; kb < 200; kb += 2) {
            float4 wa = W4[kb];
            float4 wb = W4[kb + 1];
            ulonglong2 hA = hs2[(4 * kb + 0) * 4 + q];
            ulonglong2 hB = hs2[(4 * kb + 1) * 4 + q];
            ulonglong2 hC = hs2[(4 * kb + 2) * 4 + q];
            ulonglong2 hD = hs2[(4 * kb + 3) * 4 + q];
            ulonglong2 hE = hs2[(4 * kb + 4) * 4 + q];
            ulonglong2 hF = hs2[(4 * kb + 5) * 4 + q];
            ulonglong2 hG = hs2[(4 * kb + 6) * 4 + q];
            ulonglong2 hH = hs2[(4 * kb + 7) * 4 + q];
            unsigned long long w0 = bcast2(wa.x), w1 = bcast2(wa.y);
            unsigned long long w2 = bcast2(wa.z), w3 = bcast2(wa.w);
            fma2(a0, w0, hA.x); fma2(a1, w0, hA.y);
            fma2(a0, w1, hB.x); fma2(a1, w1, hB.y);
            fma2(a0, w2, hC.x); fma2(a1, w2, hC.y);
            fma2(a0, w3, hD.x); fma2(a1, w3, hD.y);
            unsigned long long v0 = bcast2(wb.x), v1 = bcast2(wb.y);
            unsigned long long v2 = bcast2(wb.z), v3 = bcast2(wb.w);
            fma2(b0, v0, hE.x); fma2(b1, v0, hE.y);
            fma2(b0, v1, hF.x); fma2(b1, v1, hF.y);
            fma2(b0, v2, hG.x); fma2(b1, v2, hG.y);
            fma2(b0, v3, hH.x); fma2(b1, v3, hH.y);
        }
        add2(a0, b0);
        add2(a1, b1);
        float2 r0 = unpack2(a0), r1 = unpack2(a1);
        *reinterpret_cast<float4*>(gsm + gi2 * 256 + ul * 16 + q * 4) =
            make_float4(r0.x, r0.y, r1.x, r1.y);
        __syncthreads();                      // gsm ready for next phase A
    }
}

// ---------------- softmax + angle mixing + SRF (softmax denom cancels in atan2) ----------------
__global__ void phisrf(const float* __restrict__ alphabet,
                       const float* __restrict__ blen, const float* __restrict__ bang) {
    __shared__ float sA[180], cA[180];
    int tid = threadIdx.x;
    if (tid < 180) { float a = alphabet[tid]; sA[tid] = sinf(a); cA[tid] = cosf(a); }
    __syncthreads();
    int row = blockIdx.x * 256 + tid;
    if (row >= NROW) return;
    const float* z = g_logits + (size_t)row * 60;
    float mx = -1e30f;
    for (int j = 0; j < 60; j++) mx = fmaxf(mx, z[j]);
    float ss0 = 0, ss1 = 0, ss2 = 0, sc0 = 0, sc1 = 0, sc2 = 0;
    for (int j = 0; j < 60; j++) {
        float e = __expf(z[j] - mx);
        ss0 += e * sA[j * 3 + 0]; sc0 += e * cA[j * 3 + 0];
        ss1 += e * sA[j * 3 + 1]; sc1 += e * cA[j * 3 + 1];
        ss2 += e * sA[j * 3 + 2]; sc2 += e * cA[j * 3 + 2];
    }
    float ss[3] = {ss0, ss1, ss2}, sc[3] = {sc0, sc1, sc2};
    int l = row >> 4, b = row & 15;
#pragma unroll
    for (int d = 0; d < 3; d++) {
        float rh = rsqrtf(ss[d] * ss[d] + sc[d] * sc[d]);
        float cp = sc[d] * rh, sp = ss[d] * rh;       // cos/sin of atan2(ss, sc)
        float rr = blen[d], th = bang[d];
        float sth = sinf(th), cth = cosf(th);
        float* o = &g_srf[(((size_t)(3 * l + d)) * 16 + b) * 3];
        o[0] = rr * cth;
        o[1] = rr * cp * sth;
        o[2] = rr * sp * sth;
    }
}

// ---------------- pNeRF: 384 parallel scan chains + sequential fragment assembly ----------------
struct F3 { float x, y, z; };
__device__ __forceinline__ F3 mk3(float x, float y, float z) { F3 r; r.x = x; r.y = y; r.z = z; return r; }
__device__ __forceinline__ F3 sub3(F3 a, F3 b) { return mk3(a.x - b.x, a.y - b.y, a.z - b.z); }
__device__ __forceinline__ F3 crs3(F3 a, F3 b) {
    return mk3(a.y * b.z - a.z * b.y, a.z * b.x - a.x * b.z, a.x * b.y - a.y * b.x);
}
__device__ __forceinline__ F3 unit3(F3 v) {
    float r = rsqrtf(v.x * v.x + v.y * v.y + v.z * v.z);
    return mk3(v.x * r, v.y * r, v.z * r);
}

__global__ void pnerf_kernel(float* __restrict__ out) {
    __shared__ float Rm[16][9];
    __shared__ float Og[16][3];
    int tid = threadIdx.x;                     // 384 threads
    {
        int kf = tid >> 4, b = tid & 15;       // chain (fragment, batch)
        F3 A  = mk3(-0.70710678118654752f, 1.22474487139158905f, 0.f);
        F3 Bp = mk3(-1.41421356237309505f, 0.f, 0.f);
        F3 C  = mk3(0.f, 0.f, 0.f);
        for (int f = 0; f < 72; f++) {
            const float* ct = &g_srf[(((size_t)(kf * 72 + f)) * 16 + b) * 3];
            F3 bc = unit3(sub3(C, Bp));
            F3 n  = unit3(crs3(sub3(Bp, A), bc));
            F3 m  = crs3(n, bc);
            F3 D  = mk3(C.x + bc.x * ct[0] + m.x * ct[1] + n.x * ct[2],
                        C.y + bc.y * ct[0] + m.y * ct[1] + n.y * ct[2],
                        C.z + bc.z * ct[0] + m.z * ct[1] + n.z * ct[2]);
            float* fp = &g_frag[((((size_t)f) * 24 + kf) * 16 + b) * 3];
            fp[0] = D.x; fp[1] = D.y; fp[2] = D.z;
            A = Bp; Bp = C; C = D;
        }
    }
    __syncthreads();
    for (int e = tid; e < 72 * 16; e += 384) {
        int f = e >> 4, b = e & 15;
        const float* fp = &g_frag[((((size_t)f) * 24 + 0) * 16 + b) * 3];
        float* o = &out[((size_t)f * 16 + b) * 3];
        o[0] = fp[0]; o[1] = fp[1]; o[2] = fp[2];
    }
    __syncthreads();
    for (int k = 1; k < 24; k++) {
        if (tid < 16) {
            int base = 72 * k;
            const float* pa = &out[((size_t)(base - 3) * 16 + tid) * 3];
            const float* pb = &out[((size_t)(base - 2) * 16 + tid) * 3];
            const float* pc = &out[((size_t)(base - 1) * 16 + tid) * 3];
            F3 A  = mk3(pa[0], pa[1], pa[2]);
            F3 B2 = mk3(pb[0], pb[1], pb[2]);
            F3 C  = mk3(pc[0], pc[1], pc[2]);
            F3 bc = unit3(sub3(C, B2));
            F3 n  = unit3(crs3(sub3(B2, A), bc));
            F3 m  = crs3(n, bc);
            Rm[tid][0] = bc.x; Rm[tid][1] = bc.y; Rm[tid][2] = bc.z;
            Rm[tid][3] = m.x;  Rm[tid][4] = m.y;  Rm[tid][5] = m.z;
            Rm[tid][6] = n.x;  Rm[tid][7] = n.y;  Rm[tid][8] = n.z;
            Og[tid][0] = C.x;  Og[tid][1] = C.y;  Og[tid][2] = C.z;
        }
        __syncthreads();
        for (int e = tid; e < 72 * 16; e += 384) {
            int f = e >> 4, b = e & 15;
            const float* fp = &g_frag[((((size_t)f) * 24 + k) * 16 + b) * 3];
            float vx = fp[0], vy = fp[1], vz = fp[2];
            float* o = &out[((size_t)(72 * k + f) * 16 + b) * 3];
            o[0] = Og[b][0] + Rm[b][0] * vx + Rm[b][3] * vy + Rm[b][6] * vz;
            o[1] = Og[b][1] + Rm[b][1] * vx + Rm[b][4] * vy + Rm[b][7] * vz;
            o[2] = Og[b][2] + Rm[b][2] * vx + Rm[b][5] * vy + Rm[b][8] * vz;
        }
        __syncthreads();
    }
}

// ---------------- launch ----------------
extern "C" void kernel_launch(void* const* d_in, const int* in_sizes, int n_in,
                              void* d_out, int out_size) {
    const int*   seq      = (const int*)  d_in[0];
    const float* pssm     = (const float*)d_in[1];
    const float* w_ih_l0f = (const float*)d_in[3];
    const float* w_hh_l0f = (const float*)d_in[4];
    const float* b_ih_l0f = (const float*)d_in[5];
    const float* b_hh_l0f = (const float*)d_in[6];
    const float* w_ih_l0b = (const float*)d_in[7];
    const float* w_hh_l0b = (const float*)d_in[8];
    const float* b_ih_l0b = (const float*)d_in[9];
    const float* b_hh_l0b = (const float*)d_in[10];
    const float* w_ih_l1f = (const float*)d_in[11];
    const float* w_hh_l1f = (const float*)d_in[12];
    const float* b_ih_l1f = (const float*)d_in[13];
    const float* b_hh_l1f = (const float*)d_in[14];
    const float* w_ih_l1b = (const float*)d_in[15];
    const float* w_hh_l1b = (const float*)d_in[16];
    const float* b_ih_l1b = (const float*)d_in[17];
    const float* b_hh_l1b = (const float*)d_in[18];
    const float* fc_w     = (const float*)d_in[19];
    const float* fc_b     = (const float*)d_in[20];
    const float* alphabet = (const float*)d_in[21];
    const float* blen     = (const float*)d_in[22];
    const float* bang     = (const float*)d_in[23];
    float* out = (float*)d_out;

    cudaFuncSetAttribute((const void*)lstm_layer,
                         cudaFuncAttributeMaxDynamicSharedMemorySize, 55296);

    build_x<<<(NROW * 41 + 255) / 256, 256>>>(seq, pssm);

    dim3 gProj(25, 72);
    // layer 0 input projections (K=41), biases folded in, [t][gate][b] layout
    sgemm_nt<<<gProj, 256>>>(0, w_ih_l0f, b_ih_l0f, b_hh_l0f, 0, NROW, 3200, 41, 1);
    sgemm_nt<<<gProj, 256>>>(0, w_ih_l0b, b_ih_l0b, b_hh_l0b, 1, NROW, 3200, 41, 1);
    lstm_layer<<<NBLK, 256, 55296>>>(0, w_hh_l0f, w_hh_l0b);

    // layer 1 input projections (K=1600)
    sgemm_nt<<<gProj, 256>>>(1, w_ih_l1f, b_ih_l1f, b_hh_l1f, 0, NROW, 3200, 1600, 1);
    sgemm_nt<<<gProj, 256>>>(1, w_ih_l1b, b_ih_l1b, b_hh_l1b, 1, NROW, 3200, 1600, 1);
    lstm_layer<<<NBLK, 256, 55296>>>(1, w_hh_l1f, w_hh_l1b);

    // FC -> logits (standard layout)
    sgemm_nt<<<dim3(1, 72), 256>>>(2, fc_w, fc_b, nullptr, 2, NROW, 60, 1600, 0);

    phisrf<<<36, 256>>>(alphabet, blen, bang);
    pnerf_kernel<<<1, 384>>>(out);
}

// round 14
// speedup vs baseline: 1.7130x; 1.6290x over previous
#include <cuda_runtime.h>
#include <math.h>
#include <stdint.h>

#define NROW 9216   // L*B = 576*16
#define NBLK 100    // persistent grid size (<=148 SMs -> co-resident, barrier safe)

// ---------------- static device scratch (no allocations) ----------------
__device__ __align__(16) float g_x[NROW * 41];
__device__ __align__(16) float g_projF[576 * 3200 * 16];   // [t][gate][b]
__device__ __align__(16) float g_projB[576 * 3200 * 16];
__device__ __align__(16) float g_h0[NROW * 1600];          // [t*16+b][1600]
__device__ __align__(16) float g_h1[NROW * 1600];
__device__ __align__(16) float g_hbuf[2][2][12800];        // [parity][dir][u*16+b]
__device__ __align__(16) float g_logits[NROW * 60];
__device__ __align__(16) float g_srf[1728 * 16 * 3];
__device__ __align__(16) float g_frag[72 * 24 * 16 * 3];   // [f][kfrag][b][3]
// transposed recurrent weights: [layer*2+dir][k*3200 + gblk*64 + gate*16 + ul]
__device__ __align__(16) float g_WT[4][800 * 3200];

__device__ unsigned g_bar_count;   // zero-init; returns to 0 after every barrier
__device__ unsigned g_bar_phase;   // monotone across replays (equality-tested)

// ---------------- packed f32x2 helpers (2x FFMA throughput on sm_103a) ----------------
__device__ __forceinline__ void fma2(unsigned long long& acc, unsigned long long a,
                                     unsigned long long b) {
    asm("fma.rn.f32x2 %0, %1, %2, %0;" : "+l"(acc) : "l"(a), "l"(b));
}
__device__ __forceinline__ unsigned long long bcast2(float x) {
    unsigned long long r;
    asm("mov.b64 %0, {%1, %1};" : "=l"(r) : "f"(x));
    return r;
}
__device__ __forceinline__ float2 unpack2(unsigned long long v) {
    float2 r;
    asm("mov.b64 {%0, %1}, %2;" : "=f"(r.x), "=f"(r.y) : "l"(v));
    return r;
}

// ---------------- acquire/release primitives (no L1-flushing fences) ----------------
__device__ __forceinline__ unsigned atom_arrive_acqrel(unsigned* p) {
    unsigned old;
    asm volatile("atom.acq_rel.gpu.global.add.u32 %0, [%1], 1;"
                 : "=r"(old) : "l"(p) : "memory");
    return old;
}
__device__ __forceinline__ unsigned ld_acquire(const unsigned* p) {
    unsigned v;
    asm volatile("ld.acquire.gpu.global.u32 %0, [%1];" : "=r"(v) : "l"(p) : "memory");
    return v;
}
__device__ __forceinline__ unsigned ld_relaxed(const unsigned* p) {
    unsigned v;
    asm volatile("ld.relaxed.gpu.global.u32 %0, [%1];" : "=r"(v) : "l"(p) : "memory");
    return v;
}
__device__ __forceinline__ void st_release(unsigned* p, unsigned v) {
    asm volatile("st.release.gpu.global.u32 [%0], %1;" :: "l"(p), "r"(v) : "memory");
}
__device__ __forceinline__ void st_relaxed(unsigned* p, unsigned v) {
    asm volatile("st.relaxed.gpu.global.u32 [%0], %1;" :: "l"(p), "r"(v) : "memory");
}

// ---------------- fast activations (HW tanh) ----------------
__device__ __forceinline__ float fast_tanh(float x) {
    float y;
    asm("tanh.approx.f32 %0, %1;" : "=f"(y) : "f"(x));
    return y;
}
__device__ __forceinline__ float fast_sig(float x) {
    return 0.5f * fast_tanh(0.5f * x) + 0.5f;
}

// ---------------- input assembly: one_hot(seq,20) ++ pssm ----------------
__global__ void build_x(const int* __restrict__ seq, const float* __restrict__ pssm) {
    int i = blockIdx.x * blockDim.x + threadIdx.x;
    if (i >= NROW * 41) return;
    int row = i / 41, k = i - row * 41;
    float v;
    if (k < 20) v = (seq[row] == k) ? 1.0f : 0.0f;
    else        v = pssm[(size_t)row * 21 + (k - 20)];
    g_x[i] = v;
}

// ---------------- Whh transpose into per-CTA coalesced layout ----------------
// g_WT[m][k*3200 + gblk*64 + gate*16 + ul] = Whh_m[(gate*800 + gblk*16 + ul)*800 + k]
__global__ void transpose_whh(const float* __restrict__ w0, const float* __restrict__ w1,
                              const float* __restrict__ w2, const float* __restrict__ w3) {
    const float* Ws[4] = {w0, w1, w2, w3};
    const int per = 800 * 3200;
    int total = 4 * per;
    for (int i = blockIdx.x * blockDim.x + threadIdx.x; i < total;
         i += gridDim.x * blockDim.x) {
        int m = i / per;
        int o = i - m * per;
        int k = o / 3200;
        int idx = o - k * 3200;
        int gblk = idx >> 6;
        int gate = (idx >> 4) & 3;
        int ul = idx & 15;
        int r = gate * 800 + gblk * 16 + ul;
        g_WT[m][o] = Ws[m][(size_t)r * 800 + k];
    }
}

// ---------------- fp32x2 SGEMM (NT): C[m][n] = sum_k A[m][k]*B[n][k] + biases ----------------
__global__ void __launch_bounds__(256) sgemm_nt(
    int Asel, const float* __restrict__ B,
    const float* __restrict__ bias1, const float* __restrict__ bias2,
    int Csel, int M, int N, int K, int mode)
{
    __shared__ __align__(16) float As[16][128];
    __shared__ __align__(16) float Bs[16][128];
    const float* A = (Asel == 0) ? g_x : ((Asel == 1) ? g_h0 : g_h1);
    float* C = (Csel == 0) ? g_projF : ((Csel == 1) ? g_projB : g_logits);

    int tid = threadIdx.x;
    int tx = tid & 15, ty = tid >> 4;
    int mB = blockIdx.y * 128, nB = blockIdx.x * 128;
    unsigned long long acc[8][4];
#pragma unroll
    for (int i = 0; i < 8; i++)
#pragma unroll
        for (int j = 0; j < 4; j++) acc[i][j] = 0ull;

    bool k16 = ((K & 15) == 0);

    for (int k0 = 0; k0 < K; k0 += 16) {
        if (k16) {
#pragma unroll
            for (int e = 0; e < 2; e++) {
                int fid = tid + e * 256;         // 0..511
                int row = fid >> 2;              // 0..127
                int kc  = (fid & 3) << 2;        // 0,4,8,12
                float4 va = *reinterpret_cast<const float4*>(A + (size_t)(mB + row) * K + k0 + kc);
                As[kc + 0][row] = va.x; As[kc + 1][row] = va.y;
                As[kc + 2][row] = va.z; As[kc + 3][row] = va.w;
                float4 vb = make_float4(0.f, 0.f, 0.f, 0.f);
                if (nB + row < N)
                    vb = *reinterpret_cast<const float4*>(B + (size_t)(nB + row) * K + k0 + kc);
                Bs[kc + 0][row] = vb.x; Bs[kc + 1][row] = vb.y;
                Bs[kc + 2][row] = vb.z; Bs[kc + 3][row] = vb.w;
            }
        } else {
            int row = tid >> 1;
            int c0  = (tid & 1) * 8;
#pragma unroll
            for (int u = 0; u < 8; u++) {
                int k = k0 + c0 + u;
                As[c0 + u][row] = (k < K) ? A[(size_t)(mB + row) * K + k] : 0.0f;
                Bs[c0 + u][row] = (k < K && (nB + row) < N) ? B[(size_t)(nB + row) * K + k] : 0.0f;
            }
        }
        __syncthreads();
#pragma unroll
        for (int kk = 0; kk < 16; kk++) {
            float4 a0 = *reinterpret_cast<const float4*>(&As[kk][ty * 8]);
            float4 a1 = *reinterpret_cast<const float4*>(&As[kk][ty * 8 + 4]);
            ulonglong2 bL = *reinterpret_cast<const ulonglong2*>(&Bs[kk][tx * 8]);
            ulonglong2 bH = *reinterpret_cast<const ulonglong2*>(&Bs[kk][tx * 8 + 4]);
            float av[8] = {a0.x, a0.y, a0.z, a0.w, a1.x, a1.y, a1.z, a1.w};
#pragma unroll
            for (int i = 0; i < 8; i++) {
                unsigned long long ai = bcast2(av[i]);
                fma2(acc[i][0], ai, bL.x);
                fma2(acc[i][1], ai, bL.y);
                fma2(acc[i][2], ai, bH.x);
                fma2(acc[i][3], ai, bH.y);
            }
        }
        __syncthreads();
    }

#pragma unroll
    for (int i = 0; i < 8; i++) {
        int m = mB + ty * 8 + i;
#pragma unroll
        for (int j = 0; j < 4; j++) {
            float2 v2 = unpack2(acc[i][j]);
            float vv[2] = {v2.x, v2.y};
#pragma unroll
            for (int e = 0; e < 2; e++) {
                int n = nB + tx * 8 + 2 * j + e;
                if (n < N) {
                    float v = vv[e];
                    if (bias1) v += bias1[n];
                    if (bias2) v += bias2[n];
                    if (mode == 0) C[(size_t)m * N + n] = v;
                    else           C[(((size_t)(m >> 4)) * N + n) * 16 + (m & 15)] = v;
                }
            }
        }
    }
}

// ---------------- persistent bi-LSTM layer (broadcast-LDS / coalesced-W design) ----------------
// 100 CTAs: dir = bx&1, gblk = bx>>1. CTA owns 16 units = 64 gate rows.
// Warp w: ks = w&3 (k-split of 200), rh = w>>2; lane -> row_local = rh*32+lane.
// Each thread: 1 gate row x 16 batches, 200 k. W: 1 coalesced LDG.32/warp/k (1 line).
// h[k]: LDS.128 broadcast x4 (all lanes same address). k-split partials reduced in smem.
__global__ void __launch_bounds__(256, 1) lstm_layer(int layer)
{
    extern __shared__ float smem[];
    float* hs   = smem;           // [k*16+b], 12800 floats
    float* gsm  = smem + 12800;   // [row*16+b], 1024 floats (final gates)
    float* red  = smem + 13824;   // [ks*1024 + row*16 + b], 4096 floats

    int bx = blockIdx.x;
    int dir = bx & 1, gblk = bx >> 1;
    int tid = threadIdx.x;
    const float* proj = dir ? g_projB : g_projF;
    const float* WT   = g_WT[layer * 2 + dir];
    float* hseq = layer ? g_h1 : g_h0;

    unsigned my_phase = 0;
    if (tid == 0) my_phase = ld_relaxed(&g_bar_phase);

    // phase-A mapping (one h element per thread)
    int ua = tid >> 4, b = tid & 15;
    int u  = gblk * 16 + ua;
    // matmul mapping
    int w  = tid >> 5, lane = tid & 31;
    int ks = w & 3;                       // k range [ks*200, ks*200+200)
    int rh = w >> 2;
    int row_local = rh * 32 + lane;       // 0..63 (gate = row>>4, ul = row&15)
    const float* Wk = WT + (size_t)(ks * 200) * 3200 + gblk * 64 + row_local;
    // reduction mapping
    int rrow = tid >> 2, bq = tid & 3;
    int Rglob = (rrow >> 4) * 800 + gblk * 16 + (rrow & 15);

    const ulonglong2* hs2 = reinterpret_cast<const ulonglong2*>(hs);

    float c_reg = 0.0f;

    for (int s = 0; s <= 576; s++) {
        // ---- phase A: finalize h_{s-1}, c_{s-1} from own gates ----
        if (s > 0) {
            float gi = gsm[(0 * 16 + ua) * 16 + b];
            float gf = gsm[(16 + ua) * 16 + b];
            float gg = gsm[(32 + ua) * 16 + b];
            float go = gsm[(48 + ua) * 16 + b];
            float cn = fast_sig(gf) * c_reg + fast_sig(gi) * fast_tanh(gg);
            c_reg = cn;
            float h = fast_sig(go) * fast_tanh(cn);
            __stcg(&g_hbuf[(s - 1) & 1][dir][u * 16 + b], h);
            int tprev = dir ? (576 - s) : (s - 1);
            __stcg(&hseq[(size_t)(tprev * 16 + b) * 1600 + dir * 800 + u], h);
        }
        if (s == 576) break;

        // ---- flush-free grid barrier: h_{s-1} visible to all CTAs ----
        __syncthreads();
        if (tid == 0) {
            my_phase++;
            unsigned a = atom_arrive_acqrel(&g_bar_count);
            if (a == NBLK - 1u) {
                st_relaxed(&g_bar_count, 0u);
                st_release(&g_bar_phase, my_phase);
            } else {
                while (ld_acquire(&g_bar_phase) != my_phase) { }
            }
        }
        __syncthreads();

        // ---- gather h into smem (L2 path) ----
        if (s == 0) {
            for (int e4 = tid; e4 < 3200; e4 += 256)
                reinterpret_cast<float4*>(hs)[e4] = make_float4(0.f, 0.f, 0.f, 0.f);
        } else {
            const float4* hb = reinterpret_cast<const float4*>(g_hbuf[(s - 1) & 1][dir]);
            for (int e4 = tid; e4 < 3200; e4 += 256)
                reinterpret_cast<float4*>(hs)[e4] = __ldcg(hb + e4);
        }
        __syncthreads();

        // ---- partial gates: row_local x 16 batches over k in [ks*200, +200) ----
        unsigned long long acc0 = 0ull, acc1 = 0ull, acc2 = 0ull, acc3 = 0ull;
        unsigned long long acc4 = 0ull, acc5 = 0ull, acc6 = 0ull, acc7 = 0ull;
        int kbase = ks * 200;
#pragma unroll 1
        for (int kk = 0; kk < 200; kk += 8) {
            float wv[8];
#pragma unroll
            for (int j = 0; j < 8; j++)
                wv[j] = __ldcg(Wk + (size_t)(kk + j) * 3200);
#pragma unroll
            for (int j = 0; j < 8; j++) {
                int k = kbase + kk + j;
                ulonglong2 hA = hs2[k * 4 + 0];     // b0..3 (broadcast)
                ulonglong2 hB = hs2[k * 4 + 1];     // b4..7
                ulonglong2 hC = hs2[k * 4 + 2];     // b8..11
                ulonglong2 hD = hs2[k * 4 + 3];     // b12..15
                unsigned long long wp = bcast2(wv[j]);
                fma2(acc0, wp, hA.x); fma2(acc1, wp, hA.y);
                fma2(acc2, wp, hB.x); fma2(acc3, wp, hB.y);
                fma2(acc4, wp, hC.x); fma2(acc5, wp, hC.y);
                fma2(acc6, wp, hD.x); fma2(acc7, wp, hD.y);
            }
        }
        // store partials
        {
            float* dst = red + ks * 1024 + row_local * 16;
            float2 p0 = unpack2(acc0), p1 = unpack2(acc1);
            float2 p2 = unpack2(acc2), p3 = unpack2(acc3);
            float2 p4 = unpack2(acc4), p5 = unpack2(acc5);
            float2 p6 = unpack2(acc6), p7 = unpack2(acc7);
            *reinterpret_cast<float4*>(dst + 0)  = make_float4(p0.x, p0.y, p1.x, p1.y);
            *reinterpret_cast<float4*>(dst + 4)  = make_float4(p2.x, p2.y, p3.x, p3.y);
            *reinterpret_cast<float4*>(dst + 8)  = make_float4(p4.x, p4.y, p5.x, p5.y);
            *reinterpret_cast<float4*>(dst + 12) = make_float4(p6.x, p6.y, p7.x, p7.y);
        }
        __syncthreads();
        // reduce 4 k-splits + proj(+biases) -> gsm
        {
            int t = dir ? (575 - s) : s;
            float4 pv = __ldcg(reinterpret_cast<const float4*>(
                            proj + ((size_t)t * 3200 + Rglob) * 16 + bq * 4));
            int off = rrow * 16 + bq * 4;
            float4 s0 = *reinterpret_cast<const float4*>(red + 0 * 1024 + off);
            float4 s1 = *reinterpret_cast<const float4*>(red + 1 * 1024 + off);
            float4 s2 = *reinterpret_cast<const float4*>(red + 2 * 1024 + off);
            float4 s3 = *reinterpret_cast<const float4*>(red + 3 * 1024 + off);
            float4 rv;
            rv.x = pv.x + ((s0.x + s1.x) + (s2.x + s3.x));
            rv.y = pv.y + ((s0.y + s1.y) + (s2.y + s3.y));
            rv.z = pv.z + ((s0.z + s1.z) + (s2.z + s3.z));
            rv.w = pv.w + ((s0.w + s1.w) + (s2.w + s3.w));
            *reinterpret_cast<float4*>(gsm + off) = rv;
        }
        __syncthreads();                  // gsm ready for next phase A
    }
}

// ---------------- softmax + angle mixing + SRF (softmax denom cancels in atan2) ----------------
__global__ void phisrf(const float* __restrict__ alphabet,
                       const float* __restrict__ blen, const float* __restrict__ bang) {
    __shared__ float sA[180], cA[180];
    int tid = threadIdx.x;
    if (tid < 180) { float a = alphabet[tid]; sA[tid] = sinf(a); cA[tid] = cosf(a); }
    __syncthreads();
    int row = blockIdx.x * 256 + tid;
    if (row >= NROW) return;
    const float* z = g_logits + (size_t)row * 60;
    float mx = -1e30f;
    for (int j = 0; j < 60; j++) mx = fmaxf(mx, z[j]);
    float ss0 = 0, ss1 = 0, ss2 = 0, sc0 = 0, sc1 = 0, sc2 = 0;
    for (int j = 0; j < 60; j++) {
        float e = __expf(z[j] - mx);
        ss0 += e * sA[j * 3 + 0]; sc0 += e * cA[j * 3 + 0];
        ss1 += e * sA[j * 3 + 1]; sc1 += e * cA[j * 3 + 1];
        ss2 += e * sA[j * 3 + 2]; sc2 += e * cA[j * 3 + 2];
    }
    float ss[3] = {ss0, ss1, ss2}, sc[3] = {sc0, sc1, sc2};
    int l = row >> 4, b = row & 15;
#pragma unroll
    for (int d = 0; d < 3; d++) {
        float rh = rsqrtf(ss[d] * ss[d] + sc[d] * sc[d]);
        float cp = sc[d] * rh, sp = ss[d] * rh;       // cos/sin of atan2(ss, sc)
        float rr = blen[d], th = bang[d];
        float sth = sinf(th), cth = cosf(th);
        float* o = &g_srf[(((size_t)(3 * l + d)) * 16 + b) * 3];
        o[0] = rr * cth;
        o[1] = rr * cp * sth;
        o[2] = rr * sp * sth;
    }
}

// ---------------- pNeRF: 384 parallel scan chains + sequential fragment assembly ----------------
struct F3 { float x, y, z; };
__device__ __forceinline__ F3 mk3(float x, float y, float z) { F3 r; r.x = x; r.y = y; r.z = z; return r; }
__device__ __forceinline__ F3 sub3(F3 a, F3 b) { return mk3(a.x - b.x, a.y - b.y, a.z - b.z); }
__device__ __forceinline__ F3 crs3(F3 a, F3 b) {
    return mk3(a.y * b.z - a.z * b.y, a.z * b.x - a.x * b.z, a.x * b.y - a.y * b.x);
}
__device__ __forceinline__ F3 unit3(F3 v) {
    float r = rsqrtf(v.x * v.x + v.y * v.y + v.z * v.z);
    return mk3(v.x * r, v.y * r, v.z * r);
}

__global__ void pnerf_kernel(float* __restrict__ out) {
    __shared__ float Rm[16][9];
    __shared__ float Og[16][3];
    int tid = threadIdx.x;                     // 384 threads
    {
        int kf = tid >> 4, b = tid & 15;       // chain (fragment, batch)
        F3 A  = mk3(-0.70710678118654752f, 1.22474487139158905f, 0.f);
        F3 Bp = mk3(-1.41421356237309505f, 0.f, 0.f);
        F3 C  = mk3(0.f, 0.f, 0.f);
        for (int f = 0; f < 72; f++) {
            const float* ct = &g_srf[(((size_t)(kf * 72 + f)) * 16 + b) * 3];
            F3 bc = unit3(sub3(C, Bp));
            F3 n  = unit3(crs3(sub3(Bp, A), bc));
            F3 m  = crs3(n, bc);
            F3 D  = mk3(C.x + bc.x * ct[0] + m.x * ct[1] + n.x * ct[2],
                        C.y + bc.y * ct[0] + m.y * ct[1] + n.y * ct[2],
                        C.z + bc.z * ct[0] + m.z * ct[1] + n.z * ct[2]);
            float* fp = &g_frag[((((size_t)f) * 24 + kf) * 16 + b) * 3];
            fp[0] = D.x; fp[1] = D.y; fp[2] = D.z;
            A = Bp; Bp = C; C = D;
        }
    }
    __syncthreads();
    for (int e = tid; e < 72 * 16; e += 384) {
        int f = e >> 4, b = e & 15;
        const float* fp = &g_frag[((((size_t)f) * 24 + 0) * 16 + b) * 3];
        float* o = &out[((size_t)f * 16 + b) * 3];
        o[0] = fp[0]; o[1] = fp[1]; o[2] = fp[2];
    }
    __syncthreads();
    for (int k = 1; k < 24; k++) {
        if (tid < 16) {
            int base = 72 * k;
            const float* pa = &out[((size_t)(base - 3) * 16 + tid) * 3];
            const float* pb = &out[((size_t)(base - 2) * 16 + tid) * 3];
            const float* pc = &out[((size_t)(base - 1) * 16 + tid) * 3];
            F3 A  = mk3(pa[0], pa[1], pa[2]);
            F3 B2 = mk3(pb[0], pb[1], pb[2]);
            F3 C  = mk3(pc[0], pc[1], pc[2]);
            F3 bc = unit3(sub3(C, B2));
            F3 n  = unit3(crs3(sub3(B2, A), bc));
            F3 m  = crs3(n, bc);
            Rm[tid][0] = bc.x; Rm[tid][1] = bc.y; Rm[tid][2] = bc.z;
            Rm[tid][3] = m.x;  Rm[tid][4] = m.y;  Rm[tid][5] = m.z;
            Rm[tid][6] = n.x;  Rm[tid][7] = n.y;  Rm[tid][8] = n.z;
            Og[tid][0] = C.x;  Og[tid][1] = C.y;  Og[tid][2] = C.z;
        }
        __syncthreads();
        for (int e = tid; e < 72 * 16; e += 384) {
            int f = e >> 4, b = e & 15;
            const float* fp = &g_frag[((((size_t)f) * 24 + k) * 16 + b) * 3];
            float vx = fp[0], vy = fp[1], vz = fp[2];
            float* o = &out[((size_t)(72 * k + f) * 16 + b) * 3];
            o[0] = Og[b][0] + Rm[b][0] * vx + Rm[b][3] * vy + Rm[b][6] * vz;
            o[1] = Og[b][1] + Rm[b][1] * vx + Rm[b][4] * vy + Rm[b][7] * vz;
            o[2] = Og[b][2] + Rm[b][2] * vx + Rm[b][5] * vy + Rm[b][8] * vz;
        }
        __syncthreads();
    }
}

// ---------------- launch ----------------
extern "C" void kernel_launch(void* const* d_in, const int* in_sizes, int n_in,
                              void* d_out, int out_size) {
    const int*   seq      = (const int*)  d_in[0];
    const float* pssm     = (const float*)d_in[1];
    const float* w_ih_l0f = (const float*)d_in[3];
    const float* w_hh_l0f = (const float*)d_in[4];
    const float* b_ih_l0f = (const float*)d_in[5];
    const float* b_hh_l0f = (const float*)d_in[6];
    const float* w_ih_l0b = (const float*)d_in[7];
    const float* w_hh_l0b = (const float*)d_in[8];
    const float* b_ih_l0b = (const float*)d_in[9];
    const float* b_hh_l0b = (const float*)d_in[10];
    const float* w_ih_l1f = (const float*)d_in[11];
    const float* w_hh_l1f = (const float*)d_in[12];
    const float* b_ih_l1f = (const float*)d_in[13];
    const float* b_hh_l1f = (const float*)d_in[14];
    const float* w_ih_l1b = (const float*)d_in[15];
    const float* w_hh_l1b = (const float*)d_in[16];
    const float* b_ih_l1b = (const float*)d_in[17];
    const float* b_hh_l1b = (const float*)d_in[18];
    const float* fc_w     = (const float*)d_in[19];
    const float* fc_b     = (const float*)d_in[20];
    const float* alphabet = (const float*)d_in[21];
    const float* blen     = (const float*)d_in[22];
    const float* bang     = (const float*)d_in[23];
    float* out = (float*)d_out;

    cudaFuncSetAttribute((const void*)lstm_layer,
                         cudaFuncAttributeMaxDynamicSharedMemorySize, 71680);

    build_x<<<(NROW * 41 + 255) / 256, 256>>>(seq, pssm);
    transpose_whh<<<8192, 256>>>(w_hh_l0f, w_hh_l0b, w_hh_l1f, w_hh_l1b);

    dim3 gProj(25, 72);
    // layer 0 input projections (K=41), biases folded in, [t][gate][b] layout
    sgemm_nt<<<gProj, 256>>>(0, w_ih_l0f, b_ih_l0f, b_hh_l0f, 0, NROW, 3200, 41, 1);
    sgemm_nt<<<gProj, 256>>>(0, w_ih_l0b, b_ih_l0b, b_hh_l0b, 1, NROW, 3200, 41, 1);
    lstm_layer<<<NBLK, 256, 71680>>>(0);

    // layer 1 input projections (K=1600)
    sgemm_nt<<<gProj, 256>>>(1, w_ih_l1f, b_ih_l1f, b_hh_l1f, 0, NROW, 3200, 1600, 1);
    sgemm_nt<<<gProj, 256>>>(1, w_ih_l1b, b_ih_l1b, b_hh_l1b, 1, NROW, 3200, 1600, 1);
    lstm_layer<<<NBLK, 256, 71680>>>(1);

    // FC -> logits (standard layout)
    sgemm_nt<<<dim3(1, 72), 256>>>(2, fc_w, fc_b, nullptr, 2, NROW, 60, 1600, 0);

    phisrf<<<36, 256>>>(alphabet, blen, bang);
    pnerf_kernel<<<1, 384>>>(out);
}

// round 15
// speedup vs baseline: 2.0681x; 1.2073x over previous
#include <cuda_runtime.h>
#include <cuda_bf16.h>
#include <math.h>
#include <stdint.h>

#define NROW 9216   // L*B = 576*16
#define NBLK 100    // persistent grid size (<=148 SMs -> co-resident, barrier safe)

// ---------------- static device scratch (no allocations) ----------------
__device__ __align__(16) float g_x[NROW * 41];
__device__ __align__(16) float g_projF[576 * 3200 * 16];   // [t][gate][b]
__device__ __align__(16) float g_projB[576 * 3200 * 16];
__device__ __align__(16) float g_h0[NROW * 1600];          // [t*16+b][1600]
__device__ __align__(16) float g_h1[NROW * 1600];
__device__ __align__(16) float g_hbuf[2][2][12800];        // [parity][dir][u*16+b]
__device__ __align__(16) float g_logits[NROW * 60];
__device__ __align__(16) float g_srf[1728 * 16 * 3];
__device__ __align__(16) float g_frag[72 * 24 * 16 * 3];   // [f][kfrag][b][3]
// transposed recurrent weights: [layer*2+dir][k*3200 + gblk*64 + gate*16 + ul]
__device__ __align__(16) float g_WT[4][800 * 3200];

__device__ unsigned g_bar_count;
__device__ unsigned g_bar_phase;

// ---------------- packed f32x2 helpers ----------------
__device__ __forceinline__ void fma2(unsigned long long& acc, unsigned long long a,
                                     unsigned long long b) {
    asm("fma.rn.f32x2 %0, %1, %2, %0;" : "+l"(acc) : "l"(a), "l"(b));
}
__device__ __forceinline__ unsigned long long bcast2(float x) {
    unsigned long long r;
    asm("mov.b64 %0, {%1, %1};" : "=l"(r) : "f"(x));
    return r;
}
__device__ __forceinline__ float2 unpack2(unsigned long long v) {
    float2 r;
    asm("mov.b64 {%0, %1}, %2;" : "=f"(r.x), "=f"(r.y) : "l"(v));
    return r;
}

// ---------------- acquire/release primitives ----------------
__device__ __forceinline__ unsigned atom_arrive_acqrel(unsigned* p) {
    unsigned old;
    asm volatile("atom.acq_rel.gpu.global.add.u32 %0, [%1], 1;"
                 : "=r"(old) : "l"(p) : "memory");
    return old;
}
__device__ __forceinline__ unsigned ld_acquire(const unsigned* p) {
    unsigned v;
    asm volatile("ld.acquire.gpu.global.u32 %0, [%1];" : "=r"(v) : "l"(p) : "memory");
    return v;
}
__device__ __forceinline__ unsigned ld_relaxed(const unsigned* p) {
    unsigned v;
    asm volatile("ld.relaxed.gpu.global.u32 %0, [%1];" : "=r"(v) : "l"(p) : "memory");
    return v;
}
__device__ __forceinline__ void st_release(unsigned* p, unsigned v) {
    asm volatile("st.release.gpu.global.u32 [%0], %1;" :: "l"(p), "r"(v) : "memory");
}
__device__ __forceinline__ void st_relaxed(unsigned* p, unsigned v) {
    asm volatile("st.relaxed.gpu.global.u32 [%0], %1;" :: "l"(p), "r"(v) : "memory");
}

// ---------------- fast activations ----------------
__device__ __forceinline__ float fast_tanh(float x) {
    float y;
    asm("tanh.approx.f32 %0, %1;" : "=f"(y) : "f"(x));
    return y;
}
__device__ __forceinline__ float fast_sig(float x) {
    return 0.5f * fast_tanh(0.5f * x) + 0.5f;
}

// ---------------- input assembly ----------------
__global__ void build_x(const int* __restrict__ seq, const float* __restrict__ pssm) {
    int i = blockIdx.x * blockDim.x + threadIdx.x;
    if (i >= NROW * 41) return;
    int row = i / 41, k = i - row * 41;
    float v;
    if (k < 20) v = (seq[row] == k) ? 1.0f : 0.0f;
    else        v = pssm[(size_t)row * 21 + (k - 20)];
    g_x[i] = v;
}

// ---------------- Whh transpose into per-CTA coalesced layout ----------------
__global__ void transpose_whh(const float* __restrict__ w0, const float* __restrict__ w1,
                              const float* __restrict__ w2, const float* __restrict__ w3) {
    const float* Ws[4] = {w0, w1, w2, w3};
    const int per = 800 * 3200;
    int total = 4 * per;
    for (int i = blockIdx.x * blockDim.x + threadIdx.x; i < total;
         i += gridDim.x * blockDim.x) {
        int m = i / per;
        int o = i - m * per;
        int k = o / 3200;
        int idx = o - k * 3200;
        int gblk = idx >> 6;
        int gate = (idx >> 4) & 3;
        int ul = idx & 15;
        int r = gate * 800 + gblk * 16 + ul;
        g_WT[m][o] = Ws[m][(size_t)r * 800 + k];
    }
}

// ---------------- fp32x2 SGEMM (kept only for K=41 layer-0 projections) ----------------
__global__ void __launch_bounds__(256) sgemm_nt(
    int Asel, const float* __restrict__ B,
    const float* __restrict__ bias1, const float* __restrict__ bias2,
    int Csel, int M, int N, int K, int mode)
{
    __shared__ __align__(16) float As[16][128];
    __shared__ __align__(16) float Bs[16][128];
    const float* A = (Asel == 0) ? g_x : ((Asel == 1) ? g_h0 : g_h1);
    float* C = (Csel == 0) ? g_projF : ((Csel == 1) ? g_projB : g_logits);

    int tid = threadIdx.x;
    int tx = tid & 15, ty = tid >> 4;
    int mB = blockIdx.y * 128, nB = blockIdx.x * 128;
    unsigned long long acc[8][4];
#pragma unroll
    for (int i = 0; i < 8; i++)
#pragma unroll
        for (int j = 0; j < 4; j++) acc[i][j] = 0ull;

    for (int k0 = 0; k0 < K; k0 += 16) {
        int row = tid >> 1;
        int c0  = (tid & 1) * 8;
#pragma unroll
        for (int u = 0; u < 8; u++) {
            int k = k0 + c0 + u;
            As[c0 + u][row] = (k < K) ? A[(size_t)(mB + row) * K + k] : 0.0f;
            Bs[c0 + u][row] = (k < K && (nB + row) < N) ? B[(size_t)(nB + row) * K + k] : 0.0f;
        }
        __syncthreads();
#pragma unroll
        for (int kk = 0; kk < 16; kk++) {
            float4 a0 = *reinterpret_cast<const float4*>(&As[kk][ty * 8]);
            float4 a1 = *reinterpret_cast<const float4*>(&As[kk][ty * 8 + 4]);
            ulonglong2 bL = *reinterpret_cast<const ulonglong2*>(&Bs[kk][tx * 8]);
            ulonglong2 bH = *reinterpret_cast<const ulonglong2*>(&Bs[kk][tx * 8 + 4]);
            float av[8] = {a0.x, a0.y, a0.z, a0.w, a1.x, a1.y, a1.z, a1.w};
#pragma unroll
            for (int i = 0; i < 8; i++) {
                unsigned long long ai = bcast2(av[i]);
                fma2(acc[i][0], ai, bL.x);
                fma2(acc[i][1], ai, bL.y);
                fma2(acc[i][2], ai, bH.x);
                fma2(acc[i][3], ai, bH.y);
            }
        }
        __syncthreads();
    }

#pragma unroll
    for (int i = 0; i < 8; i++) {
        int m = mB + ty * 8 + i;
#pragma unroll
        for (int j = 0; j < 4; j++) {
            float2 v2 = unpack2(acc[i][j]);
            float vv[2] = {v2.x, v2.y};
#pragma unroll
            for (int e = 0; e < 2; e++) {
                int n = nB + tx * 8 + 2 * j + e;
                if (n < N) {
                    float v = vv[e];
                    if (bias1) v += bias1[n];
                    if (bias2) v += bias2[n];
                    if (mode == 0) C[(size_t)m * N + n] = v;
                    else           C[(((size_t)(m >> 4)) * N + n) * 16 + (m & 15)] = v;
                }
            }
        }
    }
}

// ---------------- split-bf16 tensor-core GEMM ----------------
// C[m][n] = sum_k A[m][k]*B[n][k] + bias, via a=ah+al, b=bh+bl (bf16),
// acc += ah*bh + ah*bl + al*bh  (al*bl ~2^-16, dropped).
// CTA tile 128(M) x 64(N), BK=32, 8 warps of 32x32. K%32==0, M%128==0.
// mode 1: proj layout [m>>4][n][m&15] via smem-transposed coalesced epilogue.
#define APITCH 40   // bf16 units; 80B rows -> conflict-free ldmatrix

__device__ __forceinline__ void ldmx4(uint32_t& r0, uint32_t& r1, uint32_t& r2,
                                      uint32_t& r3, uint32_t addr) {
    asm volatile("ldmatrix.sync.aligned.m8n8.x4.shared.b16 {%0,%1,%2,%3}, [%4];"
                 : "=r"(r0), "=r"(r1), "=r"(r2), "=r"(r3) : "r"(addr));
}
__device__ __forceinline__ void mma16816(float* d, const uint32_t* a, const uint32_t* b) {
    asm volatile(
        "mma.sync.aligned.m16n8k16.row.col.f32.bf16.bf16.f32 "
        "{%0,%1,%2,%3}, {%4,%5,%6,%7}, {%8,%9}, {%0,%1,%2,%3};"
        : "+f"(d[0]), "+f"(d[1]), "+f"(d[2]), "+f"(d[3])
        : "r"(a[0]), "r"(a[1]), "r"(a[2]), "r"(a[3]), "r"(b[0]), "r"(b[1]));
}

__global__ void __launch_bounds__(256) tgemm_bf16(
    int Asel, const float* __restrict__ B,
    const float* __restrict__ bias1, const float* __restrict__ bias2,
    int Csel, int M, int N, int K, int mode)
{
    extern __shared__ __align__(16) char smraw[];
    __nv_bfloat16* sAh = reinterpret_cast<__nv_bfloat16*>(smraw);           // 128*40*2 = 10240
    __nv_bfloat16* sAl = reinterpret_cast<__nv_bfloat16*>(smraw + 10240);
    __nv_bfloat16* sBh = reinterpret_cast<__nv_bfloat16*>(smraw + 20480);   // 64*40*2 = 5120
    __nv_bfloat16* sBl = reinterpret_cast<__nv_bfloat16*>(smraw + 25600);
    float* stage = reinterpret_cast<float*>(smraw);                          // epilogue reuse

    const float* A = (Asel == 1) ? g_h0 : g_h1;
    float* C = (Csel == 0) ? g_projF : ((Csel == 1) ? g_projB : g_logits);

    int tid = threadIdx.x;
    int lane = tid & 31;
    int w = tid >> 5;
    int wm = (w >> 1) * 32;            // 0,32,64,96
    int wn = (w & 1) * 32;             // 0,32
    int mB = blockIdx.y * 128, nB = blockIdx.x * 64;

    uint32_t smb = (uint32_t)__cvta_generic_to_shared(smraw);

    // precomputed ldmatrix lane addressing components
    int a_row = (lane & 15);
    int a_col = (lane >> 4) << 3;
    int b_row = (lane & 7) + ((lane >> 4) << 3);
    int b_col = ((lane >> 3) & 1) << 3;

    float acc[2][4][4];
#pragma unroll
    for (int mt = 0; mt < 2; mt++)
#pragma unroll
        for (int nt = 0; nt < 4; nt++)
#pragma unroll
            for (int e = 0; e < 4; e++) acc[mt][nt][e] = 0.0f;

    for (int k0 = 0; k0 < K; k0 += 32) {
        __syncthreads();
        // load + split A: 128x32 fp32 -> hi/lo bf16
#pragma unroll
        for (int e = 0; e < 4; e++) {
            int fid = tid + e * 256;
            int row = fid >> 3;
            int kq = (fid & 7) * 4;
            float4 v = *reinterpret_cast<const float4*>(A + (size_t)(mB + row) * K + k0 + kq);
            float xs[4] = {v.x, v.y, v.z, v.w};
            __nv_bfloat16 hh[4], ll[4];
#pragma unroll
            for (int j = 0; j < 4; j++) {
                hh[j] = __float2bfloat16_rn(xs[j]);
                ll[j] = __float2bfloat16_rn(xs[j] - __bfloat162float(hh[j]));
            }
            int o = row * APITCH + kq;
            *reinterpret_cast<__nv_bfloat162*>(&sAh[o])     = __halves2bfloat162(hh[0], hh[1]);
            *reinterpret_cast<__nv_bfloat162*>(&sAh[o + 2]) = __halves2bfloat162(hh[2], hh[3]);
            *reinterpret_cast<__nv_bfloat162*>(&sAl[o])     = __halves2bfloat162(ll[0], ll[1]);
            *reinterpret_cast<__nv_bfloat162*>(&sAl[o + 2]) = __halves2bfloat162(ll[2], ll[3]);
        }
        // load + split B: 64x32 fp32 (row guard for N<64)
#pragma unroll
        for (int e = 0; e < 2; e++) {
            int fid = tid + e * 256;
            int row = fid >> 3;
            int kq = (fid & 7) * 4;
            float4 v = make_float4(0.f, 0.f, 0.f, 0.f);
            if (nB + row < N)
                v = *reinterpret_cast<const float4*>(B + (size_t)(nB + row) * K + k0 + kq);
            float xs[4] = {v.x, v.y, v.z, v.w};
            __nv_bfloat16 hh[4], ll[4];
#pragma unroll
            for (int j = 0; j < 4; j++) {
                hh[j] = __float2bfloat16_rn(xs[j]);
                ll[j] = __float2bfloat16_rn(xs[j] - __bfloat162float(hh[j]));
            }
            int o = row * APITCH + kq;
            *reinterpret_cast<__nv_bfloat162*>(&sBh[o])     = __halves2bfloat162(hh[0], hh[1]);
            *reinterpret_cast<__nv_bfloat162*>(&sBh[o + 2]) = __halves2bfloat162(hh[2], hh[3]);
            *reinterpret_cast<__nv_bfloat162*>(&sBl[o])     = __halves2bfloat162(ll[0], ll[1]);
            *reinterpret_cast<__nv_bfloat162*>(&sBl[o + 2]) = __halves2bfloat162(ll[2], ll[3]);
        }
        __syncthreads();

#pragma unroll
        for (int kk = 0; kk < 32; kk += 16) {
            uint32_t Ah0[4], Ah1[4], Al0[4], Al1[4];
            uint32_t Bh[2][4], Bl[2][4];
            {
                uint32_t a0 = smb + ((wm + a_row) * APITCH + kk + a_col) * 2;
                ldmx4(Ah0[0], Ah0[1], Ah0[2], Ah0[3], a0);
                uint32_t a1 = smb + ((wm + 16 + a_row) * APITCH + kk + a_col) * 2;
                ldmx4(Ah1[0], Ah1[1], Ah1[2], Ah1[3], a1);
                ldmx4(Al0[0], Al0[1], Al0[2], Al0[3], a0 + 10240);
                ldmx4(Al1[0], Al1[1], Al1[2], Al1[3], a1 + 10240);
            }
#pragma unroll
            for (int p = 0; p < 2; p++) {
                uint32_t bo = smb + 20480 +
                    ((wn + p * 16 + b_row) * APITCH + kk + b_col) * 2;
                ldmx4(Bh[p][0], Bh[p][1], Bh[p][2], Bh[p][3], bo);
                ldmx4(Bl[p][0], Bl[p][1], Bl[p][2], Bl[p][3], bo + 5120);
            }
#pragma unroll
            for (int nt = 0; nt < 4; nt++) {
                const uint32_t* bh = &Bh[nt >> 1][(nt & 1) * 2];
                const uint32_t* bl = &Bl[nt >> 1][(nt & 1) * 2];
                mma16816(acc[0][nt], Ah0, bh);
                mma16816(acc[1][nt], Ah1, bh);
                mma16816(acc[0][nt], Ah0, bl);
                mma16816(acc[1][nt], Ah1, bl);
                mma16816(acc[0][nt], Al0, bh);
                mma16816(acc[1][nt], Al1, bh);
            }
        }
    }

    // add biases
#pragma unroll
    for (int nt = 0; nt < 4; nt++) {
        int n0 = nB + wn + nt * 8 + (lane & 3) * 2;
        float bv0 = 0.f, bv1 = 0.f;
        if (n0 < N)     { bv0 = bias1[n0];     if (bias2) bv0 += bias2[n0]; }
        if (n0 + 1 < N) { bv1 = bias1[n0 + 1]; if (bias2) bv1 += bias2[n0 + 1]; }
#pragma unroll
        for (int mt = 0; mt < 2; mt++) {
            acc[mt][nt][0] += bv0; acc[mt][nt][1] += bv1;
            acc[mt][nt][2] += bv0; acc[mt][nt][3] += bv1;
        }
    }

    if (mode == 0) {
#pragma unroll
        for (int mt = 0; mt < 2; mt++)
#pragma unroll
            for (int nt = 0; nt < 4; nt++) {
                int m = mB + wm + mt * 16 + (lane >> 2);
                int n0 = nB + wn + nt * 8 + (lane & 3) * 2;
                if (n0 < N)     C[(size_t)m * N + n0]           = acc[mt][nt][0];
                if (n0 + 1 < N) C[(size_t)m * N + n0 + 1]       = acc[mt][nt][1];
                if (n0 < N)     C[(size_t)(m + 8) * N + n0]     = acc[mt][nt][2];
                if (n0 + 1 < N) C[(size_t)(m + 8) * N + n0 + 1] = acc[mt][nt][3];
            }
        return;
    }

    // mode 1: transpose through smem, then coalesced float4 stores
    __syncthreads();   // operand smem no longer needed by any warp
    float* st = stage + w * 1056;     // 32 (nl) x 33 (ml)
#pragma unroll
    for (int mt = 0; mt < 2; mt++)
#pragma unroll
        for (int nt = 0; nt < 4; nt++) {
            int ml = mt * 16 + (lane >> 2);
            int nl = nt * 8 + (lane & 3) * 2;
            st[nl * 33 + ml]           = acc[mt][nt][0];
            st[(nl + 1) * 33 + ml]     = acc[mt][nt][1];
            st[nl * 33 + ml + 8]       = acc[mt][nt][2];
            st[(nl + 1) * 33 + ml + 8] = acc[mt][nt][3];
        }
    __syncwarp();
#pragma unroll
    for (int i = 0; i < 8; i++) {
        int t2 = i >> 2;
        int nl = (i & 3) * 8 + (lane >> 2);
        int bq = lane & 3;
        float4 v;
        v.x = st[nl * 33 + t2 * 16 + bq * 4 + 0];
        v.y = st[nl * 33 + t2 * 16 + bq * 4 + 1];
        v.z = st[nl * 33 + t2 * 16 + bq * 4 + 2];
        v.w = st[nl * 33 + t2 * 16 + bq * 4 + 3];
        int t = (mB + wm) / 16 + t2;
        int gn = nB + wn + nl;
        *reinterpret_cast<float4*>(&C[((size_t)t * N + gn) * 16 + bq * 4]) = v;
    }
}

// ---------------- persistent bi-LSTM layer (unchanged from R14) ----------------
__global__ void __launch_bounds__(256, 1) lstm_layer(int layer)
{
    extern __shared__ float smem[];
    float* hs   = smem;           // 12800 floats
    float* gsm  = smem + 12800;   // 1024
    float* red  = smem + 13824;   // 4096

    int bx = blockIdx.x;
    int dir = bx & 1, gblk = bx >> 1;
    int tid = threadIdx.x;
    const float* proj = dir ? g_projB : g_projF;
    const float* WT   = g_WT[layer * 2 + dir];
    float* hseq = layer ? g_h1 : g_h0;

    unsigned my_phase = 0;
    if (tid == 0) my_phase = ld_relaxed(&g_bar_phase);

    int ua = tid >> 4, b = tid & 15;
    int u  = gblk * 16 + ua;
    int w  = tid >> 5, lane = tid & 31;
    int ks = w & 3;
    int rh = w >> 2;
    int row_local = rh * 32 + lane;
    const float* Wk = WT + (size_t)(ks * 200) * 3200 + gblk * 64 + row_local;
    int rrow = tid >> 2, bq = tid & 3;
    int Rglob = (rrow >> 4) * 800 + gblk * 16 + (rrow & 15);

    const ulonglong2* hs2 = reinterpret_cast<const ulonglong2*>(hs);

    float c_reg = 0.0f;

    for (int s = 0; s <= 576; s++) {
        if (s > 0) {
            float gi = gsm[(0 * 16 + ua) * 16 + b];
            float gf = gsm[(16 + ua) * 16 + b];
            float gg = gsm[(32 + ua) * 16 + b];
            float go = gsm[(48 + ua) * 16 + b];
            float cn = fast_sig(gf) * c_reg + fast_sig(gi) * fast_tanh(gg);
            c_reg = cn;
            float h = fast_sig(go) * fast_tanh(cn);
            __stcg(&g_hbuf[(s - 1) & 1][dir][u * 16 + b], h);
            int tprev = dir ? (576 - s) : (s - 1);
            __stcg(&hseq[(size_t)(tprev * 16 + b) * 1600 + dir * 800 + u], h);
        }
        if (s == 576) break;

        __syncthreads();
        if (tid == 0) {
            my_phase++;
            unsigned a = atom_arrive_acqrel(&g_bar_count);
            if (a == NBLK - 1u) {
                st_relaxed(&g_bar_count, 0u);
                st_release(&g_bar_phase, my_phase);
            } else {
                while (ld_acquire(&g_bar_phase) != my_phase) { }
            }
        }
        __syncthreads();

        if (s == 0) {
            for (int e4 = tid; e4 < 3200; e4 += 256)
                reinterpret_cast<float4*>(hs)[e4] = make_float4(0.f, 0.f, 0.f, 0.f);
        } else {
            const float4* hb = reinterpret_cast<const float4*>(g_hbuf[(s - 1) & 1][dir]);
            for (int e4 = tid; e4 < 3200; e4 += 256)
                reinterpret_cast<float4*>(hs)[e4] = __ldcg(hb + e4);
        }
        __syncthreads();

        unsigned long long acc0 = 0ull, acc1 = 0ull, acc2 = 0ull, acc3 = 0ull;
        unsigned long long acc4 = 0ull, acc5 = 0ull, acc6 = 0ull, acc7 = 0ull;
        int kbase = ks * 200;
#pragma unroll 1
        for (int kk = 0; kk < 200; kk += 8) {
            float wv[8];
#pragma unroll
            for (int j = 0; j < 8; j++)
                wv[j] = __ldcg(Wk + (size_t)(kk + j) * 3200);
#pragma unroll
            for (int j = 0; j < 8; j++) {
                int k = kbase + kk + j;
                ulonglong2 hA = hs2[k * 4 + 0];
                ulonglong2 hB = hs2[k * 4 + 1];
                ulonglong2 hC = hs2[k * 4 + 2];
                ulonglong2 hD = hs2[k * 4 + 3];
                unsigned long long wp = bcast2(wv[j]);
                fma2(acc0, wp, hA.x); fma2(acc1, wp, hA.y);
                fma2(acc2, wp, hB.x); fma2(acc3, wp, hB.y);
                fma2(acc4, wp, hC.x); fma2(acc5, wp, hC.y);
                fma2(acc6, wp, hD.x); fma2(acc7, wp, hD.y);
            }
        }
        {
            float* dst = red + ks * 1024 + row_local * 16;
            float2 p0 = unpack2(acc0), p1 = unpack2(acc1);
            float2 p2 = unpack2(acc2), p3 = unpack2(acc3);
            float2 p4 = unpack2(acc4), p5 = unpack2(acc5);
            float2 p6 = unpack2(acc6), p7 = unpack2(acc7);
            *reinterpret_cast<float4*>(dst + 0)  = make_float4(p0.x, p0.y, p1.x, p1.y);
            *reinterpret_cast<float4*>(dst + 4)  = make_float4(p2.x, p2.y, p3.x, p3.y);
            *reinterpret_cast<float4*>(dst + 8)  = make_float4(p4.x, p4.y, p5.x, p5.y);
            *reinterpret_cast<float4*>(dst + 12) = make_float4(p6.x, p6.y, p7.x, p7.y);
        }
        __syncthreads();
        {
            int t = dir ? (575 - s) : s;
            float4 pv = __ldcg(reinterpret_cast<const float4*>(
                            proj + ((size_t)t * 3200 + Rglob) * 16 + bq * 4));
            int off = rrow * 16 + bq * 4;
            float4 s0 = *reinterpret_cast<const float4*>(red + 0 * 1024 + off);
            float4 s1 = *reinterpret_cast<const float4*>(red + 1 * 1024 + off);
            float4 s2 = *reinterpret_cast<const float4*>(red + 2 * 1024 + off);
            float4 s3 = *reinterpret_cast<const float4*>(red + 3 * 1024 + off);
            float4 rv;
            rv.x = pv.x + ((s0.x + s1.x) + (s2.x + s3.x));
            rv.y = pv.y + ((s0.y + s1.y) + (s2.y + s3.y));
            rv.z = pv.z + ((s0.z + s1.z) + (s2.z + s3.z));
            rv.w = pv.w + ((s0.w + s1.w) + (s2.w + s3.w));
            *reinterpret_cast<float4*>(gsm + off) = rv;
        }
        __syncthreads();
    }
}

// ---------------- softmax + angle mixing + SRF ----------------
__global__ void phisrf(const float* __restrict__ alphabet,
                       const float* __restrict__ blen, const float* __restrict__ bang) {
    __shared__ float sA[180], cA[180];
    int tid = threadIdx.x;
    if (tid < 180) { float a = alphabet[tid]; sA[tid] = sinf(a); cA[tid] = cosf(a); }
    __syncthreads();
    int row = blockIdx.x * 256 + tid;
    if (row >= NROW) return;
    const float* z = g_logits + (size_t)row * 60;
    float mx = -1e30f;
    for (int j = 0; j < 60; j++) mx = fmaxf(mx, z[j]);
    float ss0 = 0, ss1 = 0, ss2 = 0, sc0 = 0, sc1 = 0, sc2 = 0;
    for (int j = 0; j < 60; j++) {
        float e = __expf(z[j] - mx);
        ss0 += e * sA[j * 3 + 0]; sc0 += e * cA[j * 3 + 0];
        ss1 += e * sA[j * 3 + 1]; sc1 += e * cA[j * 3 + 1];
        ss2 += e * sA[j * 3 + 2]; sc2 += e * cA[j * 3 + 2];
    }
    float ss[3] = {ss0, ss1, ss2}, sc[3] = {sc0, sc1, sc2};
    int l = row >> 4, b = row & 15;
#pragma unroll
    for (int d = 0; d < 3; d++) {
        float rh = rsqrtf(ss[d] * ss[d] + sc[d] * sc[d]);
        float cp = sc[d] * rh, sp = ss[d] * rh;
        float rr = blen[d], th = bang[d];
        float sth = sinf(th), cth = cosf(th);
        float* o = &g_srf[(((size_t)(3 * l + d)) * 16 + b) * 3];
        o[0] = rr * cth;
        o[1] = rr * cp * sth;
        o[2] = rr * sp * sth;
    }
}

// ---------------- pNeRF ----------------
struct F3 { float x, y, z; };
__device__ __forceinline__ F3 mk3(float x, float y, float z) { F3 r; r.x = x; r.y = y; r.z = z; return r; }
__device__ __forceinline__ F3 sub3(F3 a, F3 b) { return mk3(a.x - b.x, a.y - b.y, a.z - b.z); }
__device__ __forceinline__ F3 crs3(F3 a, F3 b) {
    return mk3(a.y * b.z - a.z * b.y, a.z * b.x - a.x * b.z, a.x * b.y - a.y * b.x);
}
__device__ __forceinline__ F3 unit3(F3 v) {
    float r = rsqrtf(v.x * v.x + v.y * v.y + v.z * v.z);
    return mk3(v.x * r, v.y * r, v.z * r);
}

__global__ void pnerf_kernel(float* __restrict__ out) {
    __shared__ float Rm[16][9];
    __shared__ float Og[16][3];
    int tid = threadIdx.x;
    {
        int kf = tid >> 4, b = tid & 15;
        F3 A  = mk3(-0.70710678118654752f, 1.22474487139158905f, 0.f);
        F3 Bp = mk3(-1.41421356237309505f, 0.f, 0.f);
        F3 C  = mk3(0.f, 0.f, 0.f);
        for (int f = 0; f < 72; f++) {
            const float* ct = &g_srf[(((size_t)(kf * 72 + f)) * 16 + b) * 3];
            F3 bc = unit3(sub3(C, Bp));
            F3 n  = unit3(crs3(sub3(Bp, A), bc));
            F3 m  = crs3(n, bc);
            F3 D  = mk3(C.x + bc.x * ct[0] + m.x * ct[1] + n.x * ct[2],
                        C.y + bc.y * ct[0] + m.y * ct[1] + n.y * ct[2],
                        C.z + bc.z * ct[0] + m.z * ct[1] + n.z * ct[2]);
            float* fp = &g_frag[((((size_t)f) * 24 + kf) * 16 + b) * 3];
            fp[0] = D.x; fp[1] = D.y; fp[2] = D.z;
            A = Bp; Bp = C; C = D;
        }
    }
    __syncthreads();
    for (int e = tid; e < 72 * 16; e += 384) {
        int f = e >> 4, b = e & 15;
        const float* fp = &g_frag[((((size_t)f) * 24 + 0) * 16 + b) * 3];
        float* o = &out[((size_t)f * 16 + b) * 3];
        o[0] = fp[0]; o[1] = fp[1]; o[2] = fp[2];
    }
    __syncthreads();
    for (int k = 1; k < 24; k++) {
        if (tid < 16) {
            int base = 72 * k;
            const float* pa = &out[((size_t)(base - 3) * 16 + tid) * 3];
            const float* pb = &out[((size_t)(base - 2) * 16 + tid) * 3];
            const float* pc = &out[((size_t)(base - 1) * 16 + tid) * 3];
            F3 A  = mk3(pa[0], pa[1], pa[2]);
            F3 B2 = mk3(pb[0], pb[1], pb[2]);
            F3 C  = mk3(pc[0], pc[1], pc[2]);
            F3 bc = unit3(sub3(C, B2));
            F3 n  = unit3(crs3(sub3(B2, A), bc));
            F3 m  = crs3(n, bc);
            Rm[tid][0] = bc.x; Rm[tid][1] = bc.y; Rm[tid][2] = bc.z;
            Rm[tid][3] = m.x;  Rm[tid][4] = m.y;  Rm[tid][5] = m.z;
            Rm[tid][6] = n.x;  Rm[tid][7] = n.y;  Rm[tid][8] = n.z;
            Og[tid][0] = C.x;  Og[tid][1] = C.y;  Og[tid][2] = C.z;
        }
        __syncthreads();
        for (int e = tid; e < 72 * 16; e += 384) {
            int f = e >> 4, b = e & 15;
            const float* fp = &g_frag[((((size_t)f) * 24 + k) * 16 + b) * 3];
            float vx = fp[0], vy = fp[1], vz = fp[2];
            float* o = &out[((size_t)(72 * k + f) * 16 + b) * 3];
            o[0] = Og[b][0] + Rm[b][0] * vx + Rm[b][3] * vy + Rm[b][6] * vz;
            o[1] = Og[b][1] + Rm[b][1] * vx + Rm[b][4] * vy + Rm[b][7] * vz;
            o[2] = Og[b][2] + Rm[b][2] * vx + Rm[b][5] * vy + Rm[b][8] * vz;
        }
        __syncthreads();
    }
}

// ---------------- launch ----------------
extern "C" void kernel_launch(void* const* d_in, const int* in_sizes, int n_in,
                              void* d_out, int out_size) {
    const int*   seq      = (const int*)  d_in[0];
    const float* pssm     = (const float*)d_in[1];
    const float* w_ih_l0f = (const float*)d_in[3];
    const float* w_hh_l0f = (const float*)d_in[4];
    const float* b_ih_l0f = (const float*)d_in[5];
    const float* b_hh_l0f = (const float*)d_in[6];
    const float* w_ih_l0b = (const float*)d_in[7];
    const float* w_hh_l0b = (const float*)d_in[8];
    const float* b_ih_l0b = (const float*)d_in[9];
    const float* b_hh_l0b = (const float*)d_in[10];
    const float* w_ih_l1f = (const float*)d_in[11];
    const float* w_hh_l1f = (const float*)d_in[12];
    const float* b_ih_l1f = (const float*)d_in[13];
    const float* b_hh_l1f = (const float*)d_in[14];
    const float* w_ih_l1b = (const float*)d_in[15];
    const float* w_hh_l1b = (const float*)d_in[16];
    const float* b_ih_l1b = (const float*)d_in[17];
    const float* b_hh_l1b = (const float*)d_in[18];
    const float* fc_w     = (const float*)d_in[19];
    const float* fc_b     = (const float*)d_in[20];
    const float* alphabet = (const float*)d_in[21];
    const float* blen     = (const float*)d_in[22];
    const float* bang     = (const float*)d_in[23];
    float* out = (float*)d_out;

    cudaFuncSetAttribute((const void*)lstm_layer,
                         cudaFuncAttributeMaxDynamicSharedMemorySize, 71680);

    build_x<<<(NROW * 41 + 255) / 256, 256>>>(seq, pssm);
    transpose_whh<<<8192, 256>>>(w_hh_l0f, w_hh_l0b, w_hh_l1f, w_hh_l1b);

    // layer 0 input projections (K=41), fp32 path
    dim3 gProj(25, 72);
    sgemm_nt<<<gProj, 256>>>(0, w_ih_l0f, b_ih_l0f, b_hh_l0f, 0, NROW, 3200, 41, 1);
    sgemm_nt<<<gProj, 256>>>(0, w_ih_l0b, b_ih_l0b, b_hh_l0b, 1, NROW, 3200, 41, 1);
    lstm_layer<<<NBLK, 256, 71680>>>(0);

    // layer 1 input projections (K=1600), split-bf16 tensor cores
    dim3 gT(50, 72);
    tgemm_bf16<<<gT, 256, 33792>>>(1, w_ih_l1f, b_ih_l1f, b_hh_l1f, 0, NROW, 3200, 1600, 1);
    tgemm_bf16<<<gT, 256, 33792>>>(1, w_ih_l1b, b_ih_l1b, b_hh_l1b, 1, NROW, 3200, 1600, 1);
    lstm_layer<<<NBLK, 256, 71680>>>(1);

    // FC -> logits (K=1600, N=60), tensor cores, direct layout
    tgemm_bf16<<<dim3(1, 72), 256, 33792>>>(2, fc_w, fc_b, nullptr, 2, NROW, 60, 1600, 0);

    phisrf<<<36, 256>>>(alphabet, blen, bang);
    pnerf_kernel<<<1, 384>>>(out);
}